// round 6
// baseline (speedup 1.0000x reference)
#include <cuda_runtime.h>
#include <cuda_bf16.h>
#include <math.h>

// Problem constants: B=2, S=64, D=64, H=W=32, heads=8, modes 16x16
#define BSZ   128          // B*S
#define CI    64           // embed dim
#define HDIM  512          // heads*embed
#define NH    8
#define DH    64
#define NM    256          // 16x16 modes
#define NPART 32           // mode chunks for score partials (8 modes each)
#define KC    8            // GEMM k-chunk

typedef unsigned long long ull;

// ---------------- packed f32x2 helpers (Blackwell FFMA2) ---------------------
__device__ __forceinline__ ull f2u(float x, float y) {
    ull u; asm("mov.b64 %0, {%1,%2};" : "=l"(u) : "f"(x), "f"(y)); return u;
}
__device__ __forceinline__ ull bc2(float x) { return f2u(x, x); }
__device__ __forceinline__ void fma2(ull& d, ull a, ull b) {
    asm("fma.rn.f32x2 %0, %1, %2, %0;" : "+l"(d) : "l"(a), "l"(b));
}
__device__ __forceinline__ float2 u2f(ull u) {
    float2 v; asm("mov.b64 {%0,%1}, %2;" : "=f"(v.x), "=f"(v.y) : "l"(u)); return v;
}

// ---------------- static device scratch (no allocations allowed) -------------
__device__ __align__(16) float2 g_Xf [NM * CI * BSZ];       // [m][i][bs]
__device__ __align__(16) float2 g_Qf [BSZ * NM * HDIM];     // [bs][m][o]
__device__ __align__(16) float2 g_Kf [BSZ * NM * HDIM];
__device__ __align__(16) float2 g_Vf [BSZ * NM * HDIM];
__device__ __align__(16) float2 g_SAf[BSZ * NM * HDIM];
__device__ __align__(16) float2 g_Outp[4 * BSZ * CI * NM];  // 4 K-split partials
__device__ float  g_part[NPART * 16 * 64 * 64];             // [mc][bh][q][k]
__device__ __align__(16) float g_attn[16 * 64 * 64];
__device__ float  g_bias[NH * 64 * 64];

// =============================================================================
// K1: truncated forward DFT: Xf[m][i][bs] = sum_{x,y} s e^{-2pi i(kx x+ky y)/32}
// =============================================================================
__global__ __launch_bounds__(256)
void k_fwd_dft(const float* __restrict__ seq) {
    const int f = blockIdx.x;           // bs*64 + ci
    const int t = threadIdx.x;
    __shared__ float  s[1024];
    __shared__ float2 u[512];           // [x][ky]
    __shared__ ull twc[32], tws[32];
    if (t < 32) {
        float sv, cv; sincospif((float)t * (1.0f / 16.0f), &sv, &cv);
        twc[t] = f2u(cv, -sv);          // (c, -s)
        tws[t] = f2u(sv,  cv);          // (s,  c)
    }
#pragma unroll
    for (int l = 0; l < 4; ++l) s[t + l * 256] = seq[f * 1024 + t + l * 256];
    __syncthreads();
    for (int o = t; o < 512; o += 256) {
        int x = o >> 4, ky = o & 15;
        ull acc = 0;
#pragma unroll
        for (int y = 0; y < 32; ++y)
            fma2(acc, bc2(s[x * 32 + y]), twc[(ky * y) & 31]);
        u[o] = u2f(acc);
    }
    __syncthreads();
    {
        int kx = t >> 4, ky = t & 15;   // mode m = t
        ull acc = 0;
#pragma unroll
        for (int x = 0; x < 32; ++x) {
            float2 a = u[x * 16 + ky];
            int w = (kx * x) & 31;
            fma2(acc, bc2(a.x), twc[w]);
            fma2(acc, bc2(a.y), tws[w]);
        }
        int bs = f >> 6, ci = f & 63;
        g_Xf[(t * CI + ci) * BSZ + bs] = u2f(acc);
    }
}

// =============================================================================
// K2: fused QKV per-mode complex GEMM (FFMA2)
// =============================================================================
__global__ __launch_bounds__(256)
void k_qkv_gemm(const float* __restrict__ Wq, const float* __restrict__ Wk,
                const float* __restrict__ Wv) {
    const int m  = blockIdx.x;
    const int oc = blockIdx.y;
    const int z  = blockIdx.z;
    const float* W = (z == 0) ? Wq : (z == 1) ? Wk : Wv;
    float2* out    = (z == 0) ? g_Qf : (z == 1) ? g_Kf : g_Vf;
    const int t  = threadIdx.x;
    const int to = t & 15;              // o-quad
    const int tb = t >> 4;              // bs-octet
    __shared__ __align__(16) ull Xa[KC][128];
    __shared__ __align__(16) ull Xb[KC][128];
    __shared__ __align__(16) ull Wp[KC][64];
    __shared__ __align__(16) ull Wn[KC][64];
    ull acc[4][8];
#pragma unroll
    for (int a = 0; a < 4; ++a)
#pragma unroll
        for (int b = 0; b < 8; ++b) acc[a][b] = 0ULL;
    const float2* Wf2 = (const float2*)W;

    for (int i0 = 0; i0 < CI; i0 += KC) {
        __syncthreads();
#pragma unroll
        for (int l = 0; l < 4; ++l) {
            int j = t + l * 256;
            int ii = j >> 7, bs = j & 127;
            float2 x = g_Xf[(m * CI + i0 + ii) * BSZ + bs];
            Xa[ii][bs] = f2u(x.x, x.x);
            Xb[ii][bs] = f2u(x.y, x.y);
        }
#pragma unroll
        for (int l = 0; l < 2; ++l) {
            int j = t + l * 256;
            int ii = j >> 6, o = j & 63;
            float2 w = Wf2[((i0 + ii) * HDIM + oc * 64 + o) * NM + m];
            Wp[ii][o] = f2u(w.x, w.y);
            Wn[ii][o] = f2u(-w.y, w.x);
        }
        __syncthreads();
#pragma unroll
        for (int kk = 0; kk < KC; ++kk) {
            ulonglong2 w01 = *(const ulonglong2*)&Wp[kk][to * 4];
            ulonglong2 w23 = *(const ulonglong2*)&Wp[kk][to * 4 + 2];
            ulonglong2 n01 = *(const ulonglong2*)&Wn[kk][to * 4];
            ulonglong2 n23 = *(const ulonglong2*)&Wn[kk][to * 4 + 2];
            ull w[4] = {w01.x, w01.y, w23.x, w23.y};
            ull n[4] = {n01.x, n01.y, n23.x, n23.y};
            ull xa[8], xb[8];
#pragma unroll
            for (int q = 0; q < 4; ++q) {
                ulonglong2 a = *(const ulonglong2*)&Xa[kk][tb * 8 + q * 2];
                ulonglong2 b = *(const ulonglong2*)&Xb[kk][tb * 8 + q * 2];
                xa[q * 2] = a.x; xa[q * 2 + 1] = a.y;
                xb[q * 2] = b.x; xb[q * 2 + 1] = b.y;
            }
#pragma unroll
            for (int jo = 0; jo < 4; ++jo)
#pragma unroll
                for (int jb = 0; jb < 8; ++jb) {
                    fma2(acc[jo][jb], xa[jb], w[jo]);
                    fma2(acc[jo][jb], xb[jb], n[jo]);
                }
        }
    }
    float sc = 1.f; bool zim = false;
    if (z == 0) {                       // Q: Parseval weight * softmax scale
        float w = (m == 0) ? 1.f : (((m & 15) == 0) ? 0.5f : 2.f);
        sc = w * (1.f / 262144.f); zim = (m == 0);
    } else if (z == 2) {                // V: Hermitian roundtrip projection
        if (m == 0) zim = true;
        else if ((m & 15) == 0) sc = 0.5f;
    }
#pragma unroll
    for (int jb = 0; jb < 8; ++jb) {
        int bs = tb * 8 + jb;
        float2 v[4];
#pragma unroll
        for (int jo = 0; jo < 4; ++jo) {
            v[jo] = u2f(acc[jo][jb]);
            v[jo].x *= sc;
            v[jo].y = zim ? 0.f : v[jo].y * sc;
        }
        float4* dst = (float4*)&out[(bs * NM + m) * HDIM + oc * 64 + to * 4];
        dst[0] = make_float4(v[0].x, v[0].y, v[1].x, v[1].y);
        dst[1] = make_float4(v[2].x, v[2].y, v[3].x, v[3].y);
    }
}

// =============================================================================
// K3 (REWRITTEN): score partials. grid (16 bh, 32 mc of 8 modes), block 128.
// Thread tile 8q x 4k; FMA2 lanes carry dd-pairs, reduced at the end.
// Planar re/im SMEM with stride-9 float2 rows (conflict-free STS/LDS).
// =============================================================================
#define SROW 9
__global__ __launch_bounds__(128)
void k_scores(void) {
    const int bh = blockIdx.x;
    const int mc = blockIdx.y;          // 32 chunks of 8 modes
    const int b = bh >> 3, h = bh & 7;
    const int t = threadIdx.x;
    const int tq = t >> 4;              // 0..7
    const int tk = t & 15;              // 0..15
    __shared__ __align__(16) float2 Qr[64 * SROW], Qi[64 * SROW];
    __shared__ __align__(16) float2 Kr[64 * SROW], Ki[64 * SROW];
    ull acc[8][4];
#pragma unroll
    for (int i = 0; i < 8; ++i)
#pragma unroll
        for (int j = 0; j < 4; ++j) acc[i][j] = 0ULL;

    // float4 view of g_Qf/g_Kf; s-row stride in float4 units:
    const int SSTRIDE4 = NM * HDIM / 2; // 65536
    for (int mm = 0; mm < 8; ++mm) {
        const int m = mc * 8 + mm;
        const long base2 = (long)(b * 64) * NM * HDIM + (long)m * HDIM + h * DH;
        for (int d0 = 0; d0 < DH; d0 += 16) {
            const float4* Qg = (const float4*)g_Qf + ((base2 + d0) >> 1);
            const float4* Kg = (const float4*)g_Kf + ((base2 + d0) >> 1);
            __syncthreads();
#pragma unroll
            for (int l = 0; l < 4; ++l) {
                int fl = t + l * 128;   // 512 = 64 s x 8 dp
                int s = fl >> 3, dp = fl & 7;
                float4 q = Qg[(long)s * SSTRIDE4 + dp];
                float4 k = Kg[(long)s * SSTRIDE4 + dp];
                Qr[s * SROW + dp] = make_float2(q.x, q.z);
                Qi[s * SROW + dp] = make_float2(q.y, q.w);
                Kr[s * SROW + dp] = make_float2(k.x, k.z);
                Ki[s * SROW + dp] = make_float2(k.y, k.w);
            }
            __syncthreads();
#pragma unroll
            for (int dp = 0; dp < 8; ++dp) {
                ull kr[4], ki[4];
#pragma unroll
                for (int j = 0; j < 4; ++j) {
                    int row = tk + 16 * j;
                    kr[j] = *(const ull*)&Kr[row * SROW + dp];
                    ki[j] = *(const ull*)&Ki[row * SROW + dp];
                }
#pragma unroll
                for (int i = 0; i < 8; ++i) {
                    int row = tq + 8 * i;
                    ull qr = *(const ull*)&Qr[row * SROW + dp];
                    ull qi = *(const ull*)&Qi[row * SROW + dp];
#pragma unroll
                    for (int j = 0; j < 4; ++j) {
                        fma2(acc[i][j], qr, kr[j]);
                        fma2(acc[i][j], qi, ki[j]);
                    }
                }
            }
        }
    }
#pragma unroll
    for (int i = 0; i < 8; ++i)
#pragma unroll
        for (int j = 0; j < 4; ++j) {
            int q = tq + 8 * i, k = tk + 16 * j;
            float2 v = u2f(acc[i][j]);
            g_part[((mc * 16 + bh) * 64 + q) * 64 + k] = v.x + v.y;
        }
}

// =============================================================================
// K_bias: Swin-v2 log-CPB MLP -> bias[h][i][j]. grid 64 (i), block 64 (j)
// =============================================================================
__global__ __launch_bounds__(64)
void k_bias(const float* __restrict__ w1, const float* __restrict__ b1,
            const float* __restrict__ w2) {
    const int i = blockIdx.x, j = threadIdx.x;
    float dx = (float)((i >> 3) - (j >> 3));
    float dy = (float)((i & 7) - (j & 7));
    float f0 = (dx > 0.f ? 1.f : (dx < 0.f ? -1.f : 0.f)) * log1pf(fabsf(dx));
    float f1 = (dy > 0.f ? 1.f : (dy < 0.f ? -1.f : 0.f)) * log1pf(fabsf(dy));
    float acc[NH];
#pragma unroll
    for (int h = 0; h < NH; ++h) acc[h] = 0.f;
    for (int hid = 0; hid < 64; ++hid) {
        float hv = fmaxf(f0 * w1[hid] + f1 * w1[64 + hid] + b1[hid], 0.f);
#pragma unroll
        for (int h = 0; h < NH; ++h) acc[h] += hv * w2[hid * NH + h];
    }
#pragma unroll
    for (int h = 0; h < NH; ++h) g_bias[(h * 64 + i) * 64 + j] = acc[h];
}

// =============================================================================
// K4: reduce partials + bias + softmax -> attn. grid 1024 rows, block 32
// =============================================================================
__global__ __launch_bounds__(32)
void k_softmax(void) {
    const int row = blockIdx.x;         // bh*64 + q
    const int bh = row >> 6, q = row & 63;
    const int h = bh & 7;
    const int t = threadIdx.x;
    float v[2];
#pragma unroll
    for (int e = 0; e < 2; ++e) {
        int k = t + e * 32;
        float s = 0.f;
#pragma unroll
        for (int mc = 0; mc < NPART; ++mc)
            s += g_part[((mc * 16 + bh) * 64 + q) * 64 + k];
        v[e] = s + g_bias[(h * 64 + q) * 64 + k];
    }
    float mx = fmaxf(v[0], v[1]);
#pragma unroll
    for (int o = 16; o; o >>= 1) mx = fmaxf(mx, __shfl_xor_sync(0xffffffffu, mx, o));
    float e0 = __expf(v[0] - mx), e1 = __expf(v[1] - mx);
    float sm = e0 + e1;
#pragma unroll
    for (int o = 16; o; o >>= 1) sm += __shfl_xor_sync(0xffffffffu, sm, o);
    float inv = 1.f / sm;
    g_attn[row * 64 + t]      = e0 * inv;
    g_attn[row * 64 + t + 32] = e1 * inv;
}

// =============================================================================
// K5: SAf = attn @ Vf (FFMA2). grid (16 bh, 256 modes), block 256
// =============================================================================
__global__ __launch_bounds__(256)
void k_attnv(void) {
    const int bh = blockIdx.x;
    const int m  = blockIdx.y;
    const int b = bh >> 3, h = bh & 7;
    const int t = threadIdx.x;
    const int c  = t & 63;
    const int qg = t >> 6;
    __shared__ __align__(16) float  att[64][64];
    __shared__ float2 Vs[16][64];
#pragma unroll
    for (int l = 0; l < 16; ++l) {
        int j = t + l * 256;
        att[j >> 6][j & 63] = g_attn[bh * 4096 + j];
    }
    ull acc[16];
#pragma unroll
    for (int i = 0; i < 16; ++i) acc[i] = 0ULL;

    for (int k0 = 0; k0 < 64; k0 += 16) {
        __syncthreads();
#pragma unroll
        for (int l = 0; l < 4; ++l) {
            int j = t + l * 256;
            int kk = j >> 6, cc = j & 63;
            Vs[kk][cc] = g_Vf[((b * 64 + k0 + kk) * NM + m) * HDIM + h * DH + cc];
        }
        __syncthreads();
        ull vv[16];
#pragma unroll
        for (int kk = 0; kk < 16; ++kk) {
            float2 x = Vs[kk][c];
            vv[kk] = f2u(x.x, x.y);
        }
#pragma unroll
        for (int iq = 0; iq < 16; ++iq) {
            const float4* arow = (const float4*)&att[qg * 16 + iq][k0];
#pragma unroll
            for (int kq = 0; kq < 4; ++kq) {
                float4 a4 = arow[kq];
                fma2(acc[iq], bc2(a4.x), vv[kq * 4 + 0]);
                fma2(acc[iq], bc2(a4.y), vv[kq * 4 + 1]);
                fma2(acc[iq], bc2(a4.z), vv[kq * 4 + 2]);
                fma2(acc[iq], bc2(a4.w), vv[kq * 4 + 3]);
            }
        }
    }
#pragma unroll
    for (int iq = 0; iq < 16; ++iq) {
        int q = qg * 16 + iq;
        g_SAf[((b * 64 + q) * NM + m) * HDIM + h * DH + c] = u2f(acc[iq]);
    }
}

// =============================================================================
// K6: output per-mode complex GEMM (FFMA2), K-split x4
// =============================================================================
__global__ __launch_bounds__(256)
void k_outgemm(const float* __restrict__ Wo) {
    const int m   = blockIdx.x;
    const int ksp = blockIdx.y;
    const int t  = threadIdx.x;
    const int to = t & 15;
    const int tb = t >> 4;
    __shared__ __align__(16) ull Xa[KC][128];
    __shared__ __align__(16) ull Xb[KC][128];
    __shared__ __align__(16) ull Wp[KC][64];
    __shared__ __align__(16) ull Wn[KC][64];
    ull acc[4][8];
#pragma unroll
    for (int a = 0; a < 4; ++a)
#pragma unroll
        for (int b = 0; b < 8; ++b) acc[a][b] = 0ULL;
    const float2* Wf2 = (const float2*)Wo;

    const int iBeg = ksp * 128, iEnd = iBeg + 128;
    for (int i0 = iBeg; i0 < iEnd; i0 += KC) {
        __syncthreads();
#pragma unroll
        for (int l = 0; l < 4; ++l) {
            int j = t + l * 256;
            int bs = j >> 3, ii = j & 7;
            float2 x = g_SAf[(bs * NM + m) * HDIM + i0 + ii];
            Xa[ii][bs] = f2u(x.x, x.x);
            Xb[ii][bs] = f2u(x.y, x.y);
        }
#pragma unroll
        for (int l = 0; l < 2; ++l) {
            int j = t + l * 256;
            int ii = j >> 6, o = j & 63;
            float2 w = Wf2[((i0 + ii) * CI + o) * NM + m];
            Wp[ii][o] = f2u(w.x, w.y);
            Wn[ii][o] = f2u(-w.y, w.x);
        }
        __syncthreads();
#pragma unroll
        for (int kk = 0; kk < KC; ++kk) {
            ulonglong2 w01 = *(const ulonglong2*)&Wp[kk][to * 4];
            ulonglong2 w23 = *(const ulonglong2*)&Wp[kk][to * 4 + 2];
            ulonglong2 n01 = *(const ulonglong2*)&Wn[kk][to * 4];
            ulonglong2 n23 = *(const ulonglong2*)&Wn[kk][to * 4 + 2];
            ull w[4] = {w01.x, w01.y, w23.x, w23.y};
            ull n[4] = {n01.x, n01.y, n23.x, n23.y};
            ull xa[8], xb[8];
#pragma unroll
            for (int q = 0; q < 4; ++q) {
                ulonglong2 a = *(const ulonglong2*)&Xa[kk][tb * 8 + q * 2];
                ulonglong2 b = *(const ulonglong2*)&Xb[kk][tb * 8 + q * 2];
                xa[q * 2] = a.x; xa[q * 2 + 1] = a.y;
                xb[q * 2] = b.x; xb[q * 2 + 1] = b.y;
            }
#pragma unroll
            for (int jo = 0; jo < 4; ++jo)
#pragma unroll
                for (int jb = 0; jb < 8; ++jb) {
                    fma2(acc[jo][jb], xa[jb], w[jo]);
                    fma2(acc[jo][jb], xb[jb], n[jo]);
                }
        }
    }
    const int base = ksp * (BSZ * CI * NM);
#pragma unroll
    for (int jb = 0; jb < 8; ++jb) {
        int bs = tb * 8 + jb;
#pragma unroll
        for (int jo = 0; jo < 4; ++jo) {
            int co = to * 4 + jo;
            g_Outp[base + (bs * CI + co) * NM + m] = u2f(acc[jo][jb]);
        }
    }
}

// =============================================================================
// K7: truncated inverse (irfft2 semantics) + partial reduce. grid 8192 fields
// =============================================================================
__global__ __launch_bounds__(256)
void k_inv_dft(float* __restrict__ out) {
    const int f = blockIdx.x;
    const int t = threadIdx.x;
    __shared__ float2 Z[256];
    __shared__ float2 u[32][16];
    __shared__ ull twp[32], twm[32];
    if (t < 32) {
        float sv, cv; sincospif((float)t * (1.0f / 16.0f), &sv, &cv);
        twp[t] = f2u(cv, sv);
        twm[t] = f2u(-sv, cv);
    }
    {
        float2 a = g_Outp[0 * (BSZ * CI * NM) + f * NM + t];
        float2 b = g_Outp[1 * (BSZ * CI * NM) + f * NM + t];
        float2 c = g_Outp[2 * (BSZ * CI * NM) + f * NM + t];
        float2 d = g_Outp[3 * (BSZ * CI * NM) + f * NM + t];
        Z[t] = make_float2(a.x + b.x + c.x + d.x, a.y + b.y + c.y + d.y);
    }
    __syncthreads();
    for (int o = t; o < 512; o += 256) {
        int x = o >> 4, ky = o & 15;
        ull acc = 0;
#pragma unroll
        for (int kx = 0; kx < 16; ++kx) {
            float2 z = Z[kx * 16 + ky];
            int w = (kx * x) & 31;
            fma2(acc, bc2(z.x), twp[w]);
            fma2(acc, bc2(z.y), twm[w]);
        }
        u[x][ky] = u2f(acc);
    }
    __syncthreads();
#pragma unroll
    for (int r = 0; r < 4; ++r) {
        int idx = t + r * 256;
        int x = idx >> 5, y = idx & 31;
        float a = 0.5f * u[x][0].x;
#pragma unroll
        for (int ky = 1; ky < 16; ++ky) {
            float2 uv = u[x][ky];
            float2 w = u2f(twp[(ky * y) & 31]);
            a += uv.x * w.x - uv.y * w.y;
        }
        out[f * 1024 + idx] = a * (1.0f / 512.0f);
    }
}

// =============================================================================
extern "C" void kernel_launch(void* const* d_in, const int* in_sizes, int n_in,
                              void* d_out, int out_size) {
    const float* seq = (const float*)d_in[0];
    const float* wq  = (const float*)d_in[1];
    const float* wk  = (const float*)d_in[2];
    const float* wv  = (const float*)d_in[3];
    const float* wo  = (const float*)d_in[4];
    const float* w1  = (const float*)d_in[5];
    const float* b1  = (const float*)d_in[6];
    const float* w2  = (const float*)d_in[7];
    float* out = (float*)d_out;

    k_fwd_dft<<<8192, 256>>>(seq);

    dim3 gQ(256, 8, 3);
    k_qkv_gemm<<<gQ, 256>>>(wq, wk, wv);

    k_bias<<<64, 64>>>(w1, b1, w2);

    dim3 gS(16, 32);
    k_scores<<<gS, 128>>>();
    k_softmax<<<1024, 32>>>();

    dim3 gA(16, 256);
    k_attnv<<<gA, 256>>>();

    dim3 gO(256, 4);
    k_outgemm<<<gO, 256>>>(wo);
    k_inv_dft<<<8192, 256>>>(out);
}

// round 8
// speedup vs baseline: 1.5150x; 1.5150x over previous
#include <cuda_runtime.h>
#include <cuda_bf16.h>
#include <stdint.h>
#include <math.h>

// Problem constants: B=2, S=64, D=64, H=W=32, heads=8, modes 16x16
#define BSZ   128          // B*S
#define CI    64           // embed dim
#define HDIM  512          // heads*embed
#define NH    8
#define DH    64
#define NM    256          // 16x16 modes
#define NPART 32           // mode chunks for score partials (8 modes each)
#define KC    8            // GEMM k-chunk (FFMA2 kernels)

typedef unsigned long long ull;

// ---------------- packed f32x2 helpers (Blackwell FFMA2) ---------------------
__device__ __forceinline__ ull f2u(float x, float y) {
    ull u; asm("mov.b64 %0, {%1,%2};" : "=l"(u) : "f"(x), "f"(y)); return u;
}
__device__ __forceinline__ ull bc2(float x) { return f2u(x, x); }
__device__ __forceinline__ void fma2(ull& d, ull a, ull b) {
    asm("fma.rn.f32x2 %0, %1, %2, %0;" : "+l"(d) : "l"(a), "l"(b));
}
__device__ __forceinline__ float2 u2f(ull u) {
    float2 v; asm("mov.b64 {%0,%1}, %2;" : "=f"(v.x), "=f"(v.y) : "l"(u)); return v;
}

// ---------------- mma.sync bf16 helpers --------------------------------------
__device__ __forceinline__ uint32_t cvta_s(const void* p) {
    return (uint32_t)__cvta_generic_to_shared(p);
}
__device__ __forceinline__ void ldm4(uint32_t a, uint32_t& r0, uint32_t& r1,
                                     uint32_t& r2, uint32_t& r3) {
    asm volatile("ldmatrix.sync.aligned.m8n8.x4.shared.b16 {%0,%1,%2,%3},[%4];"
                 : "=r"(r0), "=r"(r1), "=r"(r2), "=r"(r3) : "r"(a));
}
__device__ __forceinline__ void ldm4t(uint32_t a, uint32_t& r0, uint32_t& r1,
                                      uint32_t& r2, uint32_t& r3) {
    asm volatile("ldmatrix.sync.aligned.m8n8.x4.trans.shared.b16 {%0,%1,%2,%3},[%4];"
                 : "=r"(r0), "=r"(r1), "=r"(r2), "=r"(r3) : "r"(a));
}
__device__ __forceinline__ void mma_bf16(float* c, const uint32_t* a,
                                         uint32_t b0, uint32_t b1) {
    asm volatile("mma.sync.aligned.m16n8k16.row.col.f32.bf16.bf16.f32 "
                 "{%0,%1,%2,%3},{%4,%5,%6,%7},{%8,%9},{%0,%1,%2,%3};"
                 : "+f"(c[0]), "+f"(c[1]), "+f"(c[2]), "+f"(c[3])
                 : "r"(a[0]), "r"(a[1]), "r"(a[2]), "r"(a[3]), "r"(b0), "r"(b1));
}

// ---------------- static device scratch (no allocations allowed) -------------
__device__ __align__(16) __nv_bfloat16 g_Xh[NM * BSZ * 128]; // [m][bs][k] hi
__device__ __align__(16) __nv_bfloat16 g_Xl[NM * BSZ * 128]; // [m][bs][k] lo
__device__ __align__(16) float2 g_Qf [BSZ * NM * HDIM];      // [bs][m][o]
__device__ __align__(16) float2 g_Kf [BSZ * NM * HDIM];
__device__ __align__(16) float2 g_Vf [BSZ * NM * HDIM];
__device__ __align__(16) float2 g_SAf[BSZ * NM * HDIM];
__device__ __align__(16) float2 g_Outp[4 * BSZ * CI * NM];   // 4 K-split partials
__device__ float  g_part[NPART * 16 * 64 * 64];              // [mc][bh][q][k]
__device__ __align__(16) float g_attn[16 * 64 * 64];
__device__ float  g_bias[NH * 64 * 64];

// =============================================================================
// K1: truncated forward DFT; emits bf16 hi/lo split planes for the MMA GEMM.
// =============================================================================
__global__ __launch_bounds__(256)
void k_fwd_dft(const float* __restrict__ seq) {
    const int f = blockIdx.x;           // bs*64 + ci
    const int t = threadIdx.x;
    __shared__ float  s[1024];
    __shared__ float2 u[512];           // [x][ky]
    __shared__ ull twc[32], tws[32];
    if (t < 32) {
        float sv, cv; sincospif((float)t * (1.0f / 16.0f), &sv, &cv);
        twc[t] = f2u(cv, -sv);          // (c, -s)
        tws[t] = f2u(sv,  cv);          // (s,  c)
    }
#pragma unroll
    for (int l = 0; l < 4; ++l) s[t + l * 256] = seq[f * 1024 + t + l * 256];
    __syncthreads();
    for (int o = t; o < 512; o += 256) {
        int x = o >> 4, ky = o & 15;
        ull acc = 0;
#pragma unroll
        for (int y = 0; y < 32; ++y)
            fma2(acc, bc2(s[x * 32 + y]), twc[(ky * y) & 31]);
        u[o] = u2f(acc);
    }
    __syncthreads();
    {
        int kx = t >> 4, ky = t & 15;   // mode m = t
        ull acc = 0;
#pragma unroll
        for (int x = 0; x < 32; ++x) {
            float2 a = u[x * 16 + ky];
            int w = (kx * x) & 31;
            fma2(acc, bc2(a.x), twc[w]);
            fma2(acc, bc2(a.y), tws[w]);
        }
        int bs = f >> 6, ci = f & 63;
        float2 v = u2f(acc);
        __nv_bfloat16 hr = __float2bfloat16(v.x);
        __nv_bfloat16 hi = __float2bfloat16(v.y);
        __nv_bfloat16 lr = __float2bfloat16(v.x - __bfloat162float(hr));
        __nv_bfloat16 li = __float2bfloat16(v.y - __bfloat162float(hi));
        int idx = (t * BSZ + bs) * 128 + 2 * ci;
        *(__nv_bfloat162*)&g_Xh[idx] = __halves2bfloat162(hr, hi);
        *(__nv_bfloat162*)&g_Xl[idx] = __halves2bfloat162(lr, li);
    }
}

// =============================================================================
// K2 (TENSOR CORE): fused QKV per-mode complex GEMM via bf16-split mma.sync.
// Per block: C[128bs x 128n] = A[128 x 128k] B[128k x 128n], n = (o,re/im),
// k = (i,re/im), B = [[Wr, Wi], [-Wi, Wr]].  C = Ah*Bh + Ah*Bl + Al*Bh.
// grid (256 modes, 8 o-chunks of 64 complex, 3 paths), block 256 (8 warps 2x4)
// =============================================================================
__global__ __launch_bounds__(256)
void k_qkv_mma(const float* __restrict__ Wq, const float* __restrict__ Wk,
               const float* __restrict__ Wv) {
    const int m  = blockIdx.x;
    const int oc = blockIdx.y;
    const int z  = blockIdx.z;
    const float2* Wf2 = (const float2*)((z == 0) ? Wq : (z == 1) ? Wk : Wv);
    float2* out = (z == 0) ? g_Qf : (z == 1) ? g_Kf : g_Vf;
    const int t = threadIdx.x;
    const int lane = t & 31, w = t >> 5;
    const int wm = w & 1, wn = w >> 1;  // warp grid 2 x 4

    __shared__ __align__(16) __nv_bfloat16 Ah[128][40];
    __shared__ __align__(16) __nv_bfloat16 Al[128][40];
    __shared__ __align__(16) __nv_bfloat16 Bh[32][136];
    __shared__ __align__(16) __nv_bfloat16 Bl[32][136];

    float acc[4][4][4];
#pragma unroll
    for (int a = 0; a < 4; ++a)
#pragma unroll
        for (int b = 0; b < 4; ++b)
#pragma unroll
            for (int c = 0; c < 4; ++c) acc[a][b][c] = 0.f;

    // ldmatrix lane address bases
    const uint32_t aAddrH = cvta_s(&Ah[wm * 64 + (lane & 15)][(lane >> 4) * 8]);
    const uint32_t aAddrL = cvta_s(&Al[wm * 64 + (lane & 15)][(lane >> 4) * 8]);
    const int brow = (lane & 7) + ((lane >> 3) & 1) * 8;
    const int bcol = wn * 32 + (lane >> 4) * 8;
    const uint32_t bAddrH = cvta_s(&Bh[brow][bcol]);
    const uint32_t bAddrL = cvta_s(&Bl[brow][bcol]);

    for (int kc = 0; kc < 4; ++kc) {
        const int k0 = kc * 32, i0 = kc * 16;
        __syncthreads();
        // A fill: 128bs x 32k bf16 (hi & lo), uint4 copies
#pragma unroll
        for (int l = 0; l < 2; ++l) {
            int idx = t + l * 256;      // 512 uint4
            int bs = idx >> 2, seg = idx & 3;
            const uint4* sh = (const uint4*)(g_Xh + (m * BSZ + bs) * 128 + k0) + seg;
            const uint4* sl = (const uint4*)(g_Xl + (m * BSZ + bs) * 128 + k0) + seg;
            *(uint4*)&Ah[bs][seg * 8] = *sh;
            *(uint4*)&Al[bs][seg * 8] = *sl;
        }
        // B fill: gather W[i][o][m] float2, split hi/lo, complex 2x2 block
#pragma unroll
        for (int l = 0; l < 4; ++l) {
            int idx = t + l * 256;      // 1024 = 16i x 64o
            int i = idx >> 6, o = idx & 63;
            float2 wv = Wf2[(((i0 + i) * HDIM) + oc * 64 + o) * NM + m];
            __nv_bfloat16 hr = __float2bfloat16(wv.x);
            __nv_bfloat16 hi = __float2bfloat16(wv.y);
            float lrf = wv.x - __bfloat162float(hr);
            float lif = wv.y - __bfloat162float(hi);
            __nv_bfloat16 lr  = __float2bfloat16(lrf);
            __nv_bfloat16 li  = __float2bfloat16(lif);
            __nv_bfloat16 nhi = __float2bfloat16(-wv.y);
            __nv_bfloat16 nli = __float2bfloat16(-lif);
            *(__nv_bfloat162*)&Bh[2 * i][2 * o]     = __halves2bfloat162(hr, hi);
            *(__nv_bfloat162*)&Bh[2 * i + 1][2 * o] = __halves2bfloat162(nhi, hr);
            *(__nv_bfloat162*)&Bl[2 * i][2 * o]     = __halves2bfloat162(lr, li);
            *(__nv_bfloat162*)&Bl[2 * i + 1][2 * o] = __halves2bfloat162(nli, lr);
        }
        __syncthreads();
#pragma unroll
        for (int ks = 0; ks < 2; ++ks) {
            uint32_t ah[4][4], al[4][4];
#pragma unroll
            for (int mt = 0; mt < 4; ++mt) {
                uint32_t off = (uint32_t)(mt * 16 * 40 + ks * 16) * 2;
                ldm4(aAddrH + off, ah[mt][0], ah[mt][1], ah[mt][2], ah[mt][3]);
                ldm4(aAddrL + off, al[mt][0], al[mt][1], al[mt][2], al[mt][3]);
            }
            uint32_t bh[4][2], bl[4][2];
#pragma unroll
            for (int np = 0; np < 2; ++np) {
                uint32_t off = (uint32_t)(ks * 16 * 136 + np * 16) * 2;
                uint32_t r0, r1, r2, r3;
                ldm4t(bAddrH + off, r0, r1, r2, r3);
                bh[np * 2][0] = r0; bh[np * 2][1] = r1;
                bh[np * 2 + 1][0] = r2; bh[np * 2 + 1][1] = r3;
                ldm4t(bAddrL + off, r0, r1, r2, r3);
                bl[np * 2][0] = r0; bl[np * 2][1] = r1;
                bl[np * 2 + 1][0] = r2; bl[np * 2 + 1][1] = r3;
            }
#pragma unroll
            for (int mt = 0; mt < 4; ++mt)
#pragma unroll
                for (int nt = 0; nt < 4; ++nt) {
                    mma_bf16(acc[mt][nt], ah[mt], bh[nt][0], bh[nt][1]);
                    mma_bf16(acc[mt][nt], ah[mt], bl[nt][0], bl[nt][1]);
                    mma_bf16(acc[mt][nt], al[mt], bh[nt][0], bh[nt][1]);
                }
        }
    }
    // epilogue: path-specific scaling, write (re,im) float2
    float sc = 1.f; bool zim = false;
    if (z == 0) {                       // Q: Parseval weight * softmax scale
        float wgt = (m == 0) ? 1.f : (((m & 15) == 0) ? 0.5f : 2.f);
        sc = wgt * (1.f / 262144.f); zim = (m == 0);
    } else if (z == 2) {                // V: Hermitian roundtrip projection
        if (m == 0) zim = true;
        else if ((m & 15) == 0) sc = 0.5f;
    }
#pragma unroll
    for (int mt = 0; mt < 4; ++mt)
#pragma unroll
        for (int nt = 0; nt < 4; ++nt) {
            int r  = wm * 64 + mt * 16 + (lane >> 2);
            int ol = oc * 64 + wn * 16 + nt * 4 + (lane & 3);
            float* a = acc[mt][nt];
            out[(r * NM + m) * HDIM + ol] =
                make_float2(a[0] * sc, zim ? 0.f : a[1] * sc);
            out[((r + 8) * NM + m) * HDIM + ol] =
                make_float2(a[2] * sc, zim ? 0.f : a[3] * sc);
        }
}

// =============================================================================
// K3: score partials. grid (16 bh, 32 mc of 8 modes), block 128.
// =============================================================================
#define SROW 9
__global__ __launch_bounds__(128)
void k_scores(void) {
    const int bh = blockIdx.x;
    const int mc = blockIdx.y;          // 32 chunks of 8 modes
    const int b = bh >> 3, h = bh & 7;
    const int t = threadIdx.x;
    const int tq = t >> 4;              // 0..7
    const int tk = t & 15;              // 0..15
    __shared__ __align__(16) float2 Qr[64 * SROW], Qi[64 * SROW];
    __shared__ __align__(16) float2 Kr[64 * SROW], Ki[64 * SROW];
    ull acc[8][4];
#pragma unroll
    for (int i = 0; i < 8; ++i)
#pragma unroll
        for (int j = 0; j < 4; ++j) acc[i][j] = 0ULL;

    const int SSTRIDE4 = NM * HDIM / 2;
    for (int mm = 0; mm < 8; ++mm) {
        const int m = mc * 8 + mm;
        const long base2 = (long)(b * 64) * NM * HDIM + (long)m * HDIM + h * DH;
        for (int d0 = 0; d0 < DH; d0 += 16) {
            const float4* Qg = (const float4*)g_Qf + ((base2 + d0) >> 1);
            const float4* Kg = (const float4*)g_Kf + ((base2 + d0) >> 1);
            __syncthreads();
#pragma unroll
            for (int l = 0; l < 4; ++l) {
                int fl = t + l * 128;
                int s = fl >> 3, dp = fl & 7;
                float4 q = Qg[(long)s * SSTRIDE4 + dp];
                float4 k = Kg[(long)s * SSTRIDE4 + dp];
                Qr[s * SROW + dp] = make_float2(q.x, q.z);
                Qi[s * SROW + dp] = make_float2(q.y, q.w);
                Kr[s * SROW + dp] = make_float2(k.x, k.z);
                Ki[s * SROW + dp] = make_float2(k.y, k.w);
            }
            __syncthreads();
#pragma unroll
            for (int dp = 0; dp < 8; ++dp) {
                ull kr[4], ki[4];
#pragma unroll
                for (int j = 0; j < 4; ++j) {
                    int row = tk + 16 * j;
                    kr[j] = *(const ull*)&Kr[row * SROW + dp];
                    ki[j] = *(const ull*)&Ki[row * SROW + dp];
                }
#pragma unroll
                for (int i = 0; i < 8; ++i) {
                    int row = tq + 8 * i;
                    ull qr = *(const ull*)&Qr[row * SROW + dp];
                    ull qi = *(const ull*)&Qi[row * SROW + dp];
#pragma unroll
                    for (int j = 0; j < 4; ++j) {
                        fma2(acc[i][j], qr, kr[j]);
                        fma2(acc[i][j], qi, ki[j]);
                    }
                }
            }
        }
    }
#pragma unroll
    for (int i = 0; i < 8; ++i)
#pragma unroll
        for (int j = 0; j < 4; ++j) {
            int q = tq + 8 * i, k = tk + 16 * j;
            float2 v = u2f(acc[i][j]);
            g_part[((mc * 16 + bh) * 64 + q) * 64 + k] = v.x + v.y;
        }
}

// =============================================================================
// K_bias: Swin-v2 log-CPB MLP -> bias[h][i][j]. grid 64 (i), block 64 (j)
// =============================================================================
__global__ __launch_bounds__(64)
void k_bias(const float* __restrict__ w1, const float* __restrict__ b1,
            const float* __restrict__ w2) {
    const int i = blockIdx.x, j = threadIdx.x;
    float dx = (float)((i >> 3) - (j >> 3));
    float dy = (float)((i & 7) - (j & 7));
    float f0 = (dx > 0.f ? 1.f : (dx < 0.f ? -1.f : 0.f)) * log1pf(fabsf(dx));
    float f1 = (dy > 0.f ? 1.f : (dy < 0.f ? -1.f : 0.f)) * log1pf(fabsf(dy));
    float acc[NH];
#pragma unroll
    for (int h = 0; h < NH; ++h) acc[h] = 0.f;
    for (int hid = 0; hid < 64; ++hid) {
        float hv = fmaxf(f0 * w1[hid] + f1 * w1[64 + hid] + b1[hid], 0.f);
#pragma unroll
        for (int h = 0; h < NH; ++h) acc[h] += hv * w2[hid * NH + h];
    }
#pragma unroll
    for (int h = 0; h < NH; ++h) g_bias[(h * 64 + i) * 64 + j] = acc[h];
}

// =============================================================================
// K4: reduce partials + bias + softmax -> attn. grid 1024 rows, block 32
// =============================================================================
__global__ __launch_bounds__(32)
void k_softmax(void) {
    const int row = blockIdx.x;
    const int bh = row >> 6, q = row & 63;
    const int h = bh & 7;
    const int t = threadIdx.x;
    float v[2];
#pragma unroll
    for (int e = 0; e < 2; ++e) {
        int k = t + e * 32;
        float s = 0.f;
#pragma unroll
        for (int mc = 0; mc < NPART; ++mc)
            s += g_part[((mc * 16 + bh) * 64 + q) * 64 + k];
        v[e] = s + g_bias[(h * 64 + q) * 64 + k];
    }
    float mx = fmaxf(v[0], v[1]);
#pragma unroll
    for (int o = 16; o; o >>= 1) mx = fmaxf(mx, __shfl_xor_sync(0xffffffffu, mx, o));
    float e0 = __expf(v[0] - mx), e1 = __expf(v[1] - mx);
    float sm = e0 + e1;
#pragma unroll
    for (int o = 16; o; o >>= 1) sm += __shfl_xor_sync(0xffffffffu, sm, o);
    float inv = 1.f / sm;
    g_attn[row * 64 + t]      = e0 * inv;
    g_attn[row * 64 + t + 32] = e1 * inv;
}

// =============================================================================
// K5: SAf = attn @ Vf (FFMA2). grid (16 bh, 256 modes), block 256
// =============================================================================
__global__ __launch_bounds__(256)
void k_attnv(void) {
    const int bh = blockIdx.x;
    const int m  = blockIdx.y;
    const int b = bh >> 3, h = bh & 7;
    const int t = threadIdx.x;
    const int c  = t & 63;
    const int qg = t >> 6;
    __shared__ __align__(16) float  att[64][64];
    __shared__ float2 Vs[16][64];
#pragma unroll
    for (int l = 0; l < 16; ++l) {
        int j = t + l * 256;
        att[j >> 6][j & 63] = g_attn[bh * 4096 + j];
    }
    ull acc[16];
#pragma unroll
    for (int i = 0; i < 16; ++i) acc[i] = 0ULL;

    for (int k0 = 0; k0 < 64; k0 += 16) {
        __syncthreads();
#pragma unroll
        for (int l = 0; l < 4; ++l) {
            int j = t + l * 256;
            int kk = j >> 6, cc = j & 63;
            Vs[kk][cc] = g_Vf[((b * 64 + k0 + kk) * NM + m) * HDIM + h * DH + cc];
        }
        __syncthreads();
        ull vv[16];
#pragma unroll
        for (int kk = 0; kk < 16; ++kk) {
            float2 x = Vs[kk][c];
            vv[kk] = f2u(x.x, x.y);
        }
#pragma unroll
        for (int iq = 0; iq < 16; ++iq) {
            const float4* arow = (const float4*)&att[qg * 16 + iq][k0];
#pragma unroll
            for (int kq = 0; kq < 4; ++kq) {
                float4 a4 = arow[kq];
                fma2(acc[iq], bc2(a4.x), vv[kq * 4 + 0]);
                fma2(acc[iq], bc2(a4.y), vv[kq * 4 + 1]);
                fma2(acc[iq], bc2(a4.z), vv[kq * 4 + 2]);
                fma2(acc[iq], bc2(a4.w), vv[kq * 4 + 3]);
            }
        }
    }
#pragma unroll
    for (int iq = 0; iq < 16; ++iq) {
        int q = qg * 16 + iq;
        g_SAf[((b * 64 + q) * NM + m) * HDIM + h * DH + c] = u2f(acc[iq]);
    }
}

// =============================================================================
// K6: output per-mode complex GEMM (FFMA2), K-split x4
// =============================================================================
__global__ __launch_bounds__(256)
void k_outgemm(const float* __restrict__ Wo) {
    const int m   = blockIdx.x;
    const int ksp = blockIdx.y;
    const int t  = threadIdx.x;
    const int to = t & 15;
    const int tb = t >> 4;
    __shared__ __align__(16) ull Xa[KC][128];
    __shared__ __align__(16) ull Xb[KC][128];
    __shared__ __align__(16) ull Wp[KC][64];
    __shared__ __align__(16) ull Wn[KC][64];
    ull acc[4][8];
#pragma unroll
    for (int a = 0; a < 4; ++a)
#pragma unroll
        for (int b = 0; b < 8; ++b) acc[a][b] = 0ULL;
    const float2* Wf2 = (const float2*)Wo;

    const int iBeg = ksp * 128, iEnd = iBeg + 128;
    for (int i0 = iBeg; i0 < iEnd; i0 += KC) {
        __syncthreads();
#pragma unroll
        for (int l = 0; l < 4; ++l) {
            int j = t + l * 256;
            int bs = j >> 3, ii = j & 7;
            float2 x = g_SAf[(bs * NM + m) * HDIM + i0 + ii];
            Xa[ii][bs] = f2u(x.x, x.x);
            Xb[ii][bs] = f2u(x.y, x.y);
        }
#pragma unroll
        for (int l = 0; l < 2; ++l) {
            int j = t + l * 256;
            int ii = j >> 6, o = j & 63;
            float2 w = Wf2[((i0 + ii) * CI + o) * NM + m];
            Wp[ii][o] = f2u(w.x, w.y);
            Wn[ii][o] = f2u(-w.y, w.x);
        }
        __syncthreads();
#pragma unroll
        for (int kk = 0; kk < KC; ++kk) {
            ulonglong2 w01 = *(const ulonglong2*)&Wp[kk][to * 4];
            ulonglong2 w23 = *(const ulonglong2*)&Wp[kk][to * 4 + 2];
            ulonglong2 n01 = *(const ulonglong2*)&Wn[kk][to * 4];
            ulonglong2 n23 = *(const ulonglong2*)&Wn[kk][to * 4 + 2];
            ull w[4] = {w01.x, w01.y, w23.x, w23.y};
            ull n[4] = {n01.x, n01.y, n23.x, n23.y};
            ull xa[8], xb[8];
#pragma unroll
            for (int q = 0; q < 4; ++q) {
                ulonglong2 a = *(const ulonglong2*)&Xa[kk][tb * 8 + q * 2];
                ulonglong2 b = *(const ulonglong2*)&Xb[kk][tb * 8 + q * 2];
                xa[q * 2] = a.x; xa[q * 2 + 1] = a.y;
                xb[q * 2] = b.x; xb[q * 2 + 1] = b.y;
            }
#pragma unroll
            for (int jo = 0; jo < 4; ++jo)
#pragma unroll
                for (int jb = 0; jb < 8; ++jb) {
                    fma2(acc[jo][jb], xa[jb], w[jo]);
                    fma2(acc[jo][jb], xb[jb], n[jo]);
                }
        }
    }
    const int base = ksp * (BSZ * CI * NM);
#pragma unroll
    for (int jb = 0; jb < 8; ++jb) {
        int bs = tb * 8 + jb;
#pragma unroll
        for (int jo = 0; jo < 4; ++jo) {
            int co = to * 4 + jo;
            g_Outp[base + (bs * CI + co) * NM + m] = u2f(acc[jo][jb]);
        }
    }
}

// =============================================================================
// K7: truncated inverse (irfft2 semantics) + partial reduce. grid 8192 fields
// =============================================================================
__global__ __launch_bounds__(256)
void k_inv_dft(float* __restrict__ out) {
    const int f = blockIdx.x;
    const int t = threadIdx.x;
    __shared__ float2 Z[256];
    __shared__ float2 u[32][16];
    __shared__ ull twp[32], twm[32];
    if (t < 32) {
        float sv, cv; sincospif((float)t * (1.0f / 16.0f), &sv, &cv);
        twp[t] = f2u(cv, sv);
        twm[t] = f2u(-sv, cv);
    }
    {
        float2 a = g_Outp[0 * (BSZ * CI * NM) + f * NM + t];
        float2 b = g_Outp[1 * (BSZ * CI * NM) + f * NM + t];
        float2 c = g_Outp[2 * (BSZ * CI * NM) + f * NM + t];
        float2 d = g_Outp[3 * (BSZ * CI * NM) + f * NM + t];
        Z[t] = make_float2(a.x + b.x + c.x + d.x, a.y + b.y + c.y + d.y);
    }
    __syncthreads();
    for (int o = t; o < 512; o += 256) {
        int x = o >> 4, ky = o & 15;
        ull acc = 0;
#pragma unroll
        for (int kx = 0; kx < 16; ++kx) {
            float2 z = Z[kx * 16 + ky];
            int w = (kx * x) & 31;
            fma2(acc, bc2(z.x), twp[w]);
            fma2(acc, bc2(z.y), twm[w]);
        }
        u[x][ky] = u2f(acc);
    }
    __syncthreads();
#pragma unroll
    for (int r = 0; r < 4; ++r) {
        int idx = t + r * 256;
        int x = idx >> 5, y = idx & 31;
        float a = 0.5f * u[x][0].x;
#pragma unroll
        for (int ky = 1; ky < 16; ++ky) {
            float2 uv = u[x][ky];
            float2 w = u2f(twp[(ky * y) & 31]);
            a += uv.x * w.x - uv.y * w.y;
        }
        out[f * 1024 + idx] = a * (1.0f / 512.0f);
    }
}

// =============================================================================
extern "C" void kernel_launch(void* const* d_in, const int* in_sizes, int n_in,
                              void* d_out, int out_size) {
    const float* seq = (const float*)d_in[0];
    const float* wq  = (const float*)d_in[1];
    const float* wk  = (const float*)d_in[2];
    const float* wv  = (const float*)d_in[3];
    const float* wo  = (const float*)d_in[4];
    const float* w1  = (const float*)d_in[5];
    const float* b1  = (const float*)d_in[6];
    const float* w2  = (const float*)d_in[7];
    float* out = (float*)d_out;

    k_fwd_dft<<<8192, 256>>>(seq);

    dim3 gQ(256, 8, 3);
    k_qkv_mma<<<gQ, 256>>>(wq, wk, wv);

    k_bias<<<64, 64>>>(w1, b1, w2);

    dim3 gS(16, 32);
    k_scores<<<gS, 128>>>();
    k_softmax<<<1024, 32>>>();

    dim3 gA(16, 256);
    k_attnv<<<gA, 256>>>();

    dim3 gO(256, 4);
    k_outgemm<<<gO, 256>>>(wo);
    k_inv_dft<<<8192, 256>>>(out);
}

// round 9
// speedup vs baseline: 1.8757x; 1.2381x over previous
#include <cuda_runtime.h>
#include <cuda_bf16.h>
#include <stdint.h>
#include <math.h>

// Problem constants: B=2, S=64, D=64, H=W=32, heads=8, modes 16x16
#define BSZ   128          // B*S
#define CI    64           // embed dim
#define HDIM  512          // heads*embed
#define NH    8
#define DH    64
#define NM    256          // 16x16 modes
#define NPART 32           // mode chunks for score partials (8 modes each)

typedef unsigned long long ull;

// ---------------- packed f32x2 helpers (Blackwell FFMA2) ---------------------
__device__ __forceinline__ ull f2u(float x, float y) {
    ull u; asm("mov.b64 %0, {%1,%2};" : "=l"(u) : "f"(x), "f"(y)); return u;
}
__device__ __forceinline__ ull bc2(float x) { return f2u(x, x); }
__device__ __forceinline__ void fma2(ull& d, ull a, ull b) {
    asm("fma.rn.f32x2 %0, %1, %2, %0;" : "+l"(d) : "l"(a), "l"(b));
}
__device__ __forceinline__ float2 u2f(ull u) {
    float2 v; asm("mov.b64 {%0,%1}, %2;" : "=f"(v.x), "=f"(v.y) : "l"(u)); return v;
}

// ---------------- mma.sync bf16 helpers --------------------------------------
__device__ __forceinline__ uint32_t cvta_s(const void* p) {
    return (uint32_t)__cvta_generic_to_shared(p);
}
__device__ __forceinline__ void ldm4(uint32_t a, uint32_t& r0, uint32_t& r1,
                                     uint32_t& r2, uint32_t& r3) {
    asm volatile("ldmatrix.sync.aligned.m8n8.x4.shared.b16 {%0,%1,%2,%3},[%4];"
                 : "=r"(r0), "=r"(r1), "=r"(r2), "=r"(r3) : "r"(a));
}
__device__ __forceinline__ void ldm4t(uint32_t a, uint32_t& r0, uint32_t& r1,
                                      uint32_t& r2, uint32_t& r3) {
    asm volatile("ldmatrix.sync.aligned.m8n8.x4.trans.shared.b16 {%0,%1,%2,%3},[%4];"
                 : "=r"(r0), "=r"(r1), "=r"(r2), "=r"(r3) : "r"(a));
}
__device__ __forceinline__ void mma_bf16(float* c, const uint32_t* a,
                                         uint32_t b0, uint32_t b1) {
    asm volatile("mma.sync.aligned.m16n8k16.row.col.f32.bf16.bf16.f32 "
                 "{%0,%1,%2,%3},{%4,%5,%6,%7},{%8,%9},{%0,%1,%2,%3};"
                 : "+f"(c[0]), "+f"(c[1]), "+f"(c[2]), "+f"(c[3])
                 : "r"(a[0]), "r"(a[1]), "r"(a[2]), "r"(a[3]), "r"(b0), "r"(b1));
}

// ---------------- static device scratch (no allocations allowed) -------------
__device__ __align__(16) __nv_bfloat16 g_Xh[NM * BSZ * 128]; // [m][bs][k] hi
__device__ __align__(16) __nv_bfloat16 g_Xl[NM * BSZ * 128]; // [m][bs][k] lo
__device__ __align__(16) float2 g_Qf [BSZ * NM * HDIM];      // [bs][m][o]
__device__ __align__(16) float2 g_Kf [BSZ * NM * HDIM];
__device__ __align__(16) float2 g_Vf [BSZ * NM * HDIM];
__device__ __align__(16) __nv_bfloat16 g_SAh[NM * BSZ * 1024]; // [m][bs][2i] hi
__device__ __align__(16) __nv_bfloat16 g_SAl[NM * BSZ * 1024]; // [m][bs][2i] lo
__device__ __align__(16) float2 g_Outp[4 * BSZ * CI * NM];   // 4 K-split partials
__device__ float  g_part[NPART * 16 * 64 * 64];              // [mc][bh][q][k]
__device__ __align__(16) float g_attn[16 * 64 * 64];
__device__ float  g_bias[NH * 64 * 64];

// =============================================================================
// K1: truncated forward DFT; emits bf16 hi/lo split planes for the MMA GEMM.
// =============================================================================
__global__ __launch_bounds__(256)
void k_fwd_dft(const float* __restrict__ seq) {
    const int f = blockIdx.x;           // bs*64 + ci
    const int t = threadIdx.x;
    __shared__ float  s[1024];
    __shared__ float2 u[512];           // [x][ky]
    __shared__ ull twc[32], tws[32];
    if (t < 32) {
        float sv, cv; sincospif((float)t * (1.0f / 16.0f), &sv, &cv);
        twc[t] = f2u(cv, -sv);          // (c, -s)
        tws[t] = f2u(sv,  cv);          // (s,  c)
    }
#pragma unroll
    for (int l = 0; l < 4; ++l) s[t + l * 256] = seq[f * 1024 + t + l * 256];
    __syncthreads();
    for (int o = t; o < 512; o += 256) {
        int x = o >> 4, ky = o & 15;
        ull acc = 0;
#pragma unroll
        for (int y = 0; y < 32; ++y)
            fma2(acc, bc2(s[x * 32 + y]), twc[(ky * y) & 31]);
        u[o] = u2f(acc);
    }
    __syncthreads();
    {
        int kx = t >> 4, ky = t & 15;   // mode m = t
        ull acc = 0;
#pragma unroll
        for (int x = 0; x < 32; ++x) {
            float2 a = u[x * 16 + ky];
            int w = (kx * x) & 31;
            fma2(acc, bc2(a.x), twc[w]);
            fma2(acc, bc2(a.y), tws[w]);
        }
        int bs = f >> 6, ci = f & 63;
        float2 v = u2f(acc);
        __nv_bfloat16 hr = __float2bfloat16(v.x);
        __nv_bfloat16 hi = __float2bfloat16(v.y);
        __nv_bfloat16 lr = __float2bfloat16(v.x - __bfloat162float(hr));
        __nv_bfloat16 li = __float2bfloat16(v.y - __bfloat162float(hi));
        int idx = (t * BSZ + bs) * 128 + 2 * ci;
        *(__nv_bfloat162*)&g_Xh[idx] = __halves2bfloat162(hr, hi);
        *(__nv_bfloat162*)&g_Xl[idx] = __halves2bfloat162(lr, li);
    }
}

// =============================================================================
// K2 (TENSOR CORE): fused QKV per-mode complex GEMM via bf16-split mma.sync.
// grid (256 modes, 8 o-chunks of 64 complex, 3 paths), block 256 (8 warps 2x4)
// =============================================================================
__global__ __launch_bounds__(256)
void k_qkv_mma(const float* __restrict__ Wq, const float* __restrict__ Wk,
               const float* __restrict__ Wv) {
    const int m  = blockIdx.x;
    const int oc = blockIdx.y;
    const int z  = blockIdx.z;
    const float2* Wf2 = (const float2*)((z == 0) ? Wq : (z == 1) ? Wk : Wv);
    float2* out = (z == 0) ? g_Qf : (z == 1) ? g_Kf : g_Vf;
    const int t = threadIdx.x;
    const int lane = t & 31, w = t >> 5;
    const int wm = w & 1, wn = w >> 1;  // warp grid 2 x 4

    __shared__ __align__(16) __nv_bfloat16 Ah[128][40];
    __shared__ __align__(16) __nv_bfloat16 Al[128][40];
    __shared__ __align__(16) __nv_bfloat16 Bh[32][136];
    __shared__ __align__(16) __nv_bfloat16 Bl[32][136];

    float acc[4][4][4];
#pragma unroll
    for (int a = 0; a < 4; ++a)
#pragma unroll
        for (int b = 0; b < 4; ++b)
#pragma unroll
            for (int c = 0; c < 4; ++c) acc[a][b][c] = 0.f;

    const uint32_t aAddrH = cvta_s(&Ah[wm * 64 + (lane & 15)][(lane >> 4) * 8]);
    const uint32_t aAddrL = cvta_s(&Al[wm * 64 + (lane & 15)][(lane >> 4) * 8]);
    const int brow = (lane & 7) + ((lane >> 3) & 1) * 8;
    const int bcol = wn * 32 + (lane >> 4) * 8;
    const uint32_t bAddrH = cvta_s(&Bh[brow][bcol]);
    const uint32_t bAddrL = cvta_s(&Bl[brow][bcol]);

    for (int kc = 0; kc < 4; ++kc) {
        const int k0 = kc * 32, i0 = kc * 16;
        __syncthreads();
#pragma unroll
        for (int l = 0; l < 2; ++l) {
            int idx = t + l * 256;      // 512 uint4
            int bs = idx >> 2, seg = idx & 3;
            const uint4* sh = (const uint4*)(g_Xh + (m * BSZ + bs) * 128 + k0) + seg;
            const uint4* sl = (const uint4*)(g_Xl + (m * BSZ + bs) * 128 + k0) + seg;
            *(uint4*)&Ah[bs][seg * 8] = *sh;
            *(uint4*)&Al[bs][seg * 8] = *sl;
        }
#pragma unroll
        for (int l = 0; l < 4; ++l) {
            int idx = t + l * 256;      // 1024 = 16i x 64o
            int i = idx >> 6, o = idx & 63;
            float2 wv = Wf2[(((i0 + i) * HDIM) + oc * 64 + o) * NM + m];
            __nv_bfloat16 hr = __float2bfloat16(wv.x);
            __nv_bfloat16 hi = __float2bfloat16(wv.y);
            float lrf = wv.x - __bfloat162float(hr);
            float lif = wv.y - __bfloat162float(hi);
            __nv_bfloat16 lr  = __float2bfloat16(lrf);
            __nv_bfloat16 li  = __float2bfloat16(lif);
            __nv_bfloat16 nhi = __float2bfloat16(-wv.y);
            __nv_bfloat16 nli = __float2bfloat16(-lif);
            *(__nv_bfloat162*)&Bh[2 * i][2 * o]     = __halves2bfloat162(hr, hi);
            *(__nv_bfloat162*)&Bh[2 * i + 1][2 * o] = __halves2bfloat162(nhi, hr);
            *(__nv_bfloat162*)&Bl[2 * i][2 * o]     = __halves2bfloat162(lr, li);
            *(__nv_bfloat162*)&Bl[2 * i + 1][2 * o] = __halves2bfloat162(nli, lr);
        }
        __syncthreads();
#pragma unroll
        for (int ks = 0; ks < 2; ++ks) {
            uint32_t ah[4][4], al[4][4];
#pragma unroll
            for (int mt = 0; mt < 4; ++mt) {
                uint32_t off = (uint32_t)(mt * 16 * 40 + ks * 16) * 2;
                ldm4(aAddrH + off, ah[mt][0], ah[mt][1], ah[mt][2], ah[mt][3]);
                ldm4(aAddrL + off, al[mt][0], al[mt][1], al[mt][2], al[mt][3]);
            }
            uint32_t bh[4][2], bl[4][2];
#pragma unroll
            for (int np = 0; np < 2; ++np) {
                uint32_t off = (uint32_t)(ks * 16 * 136 + np * 16) * 2;
                uint32_t r0, r1, r2, r3;
                ldm4t(bAddrH + off, r0, r1, r2, r3);
                bh[np * 2][0] = r0; bh[np * 2][1] = r1;
                bh[np * 2 + 1][0] = r2; bh[np * 2 + 1][1] = r3;
                ldm4t(bAddrL + off, r0, r1, r2, r3);
                bl[np * 2][0] = r0; bl[np * 2][1] = r1;
                bl[np * 2 + 1][0] = r2; bl[np * 2 + 1][1] = r3;
            }
#pragma unroll
            for (int mt = 0; mt < 4; ++mt)
#pragma unroll
                for (int nt = 0; nt < 4; ++nt) {
                    mma_bf16(acc[mt][nt], ah[mt], bh[nt][0], bh[nt][1]);
                    mma_bf16(acc[mt][nt], ah[mt], bl[nt][0], bl[nt][1]);
                    mma_bf16(acc[mt][nt], al[mt], bh[nt][0], bh[nt][1]);
                }
        }
    }
    float sc = 1.f; bool zim = false;
    if (z == 0) {                       // Q: Parseval weight * softmax scale
        float wgt = (m == 0) ? 1.f : (((m & 15) == 0) ? 0.5f : 2.f);
        sc = wgt * (1.f / 262144.f); zim = (m == 0);
    } else if (z == 2) {                // V: Hermitian roundtrip projection
        if (m == 0) zim = true;
        else if ((m & 15) == 0) sc = 0.5f;
    }
#pragma unroll
    for (int mt = 0; mt < 4; ++mt)
#pragma unroll
        for (int nt = 0; nt < 4; ++nt) {
            int r  = wm * 64 + mt * 16 + (lane >> 2);
            int ol = oc * 64 + wn * 16 + nt * 4 + (lane & 3);
            float* a = acc[mt][nt];
            out[(r * NM + m) * HDIM + ol] =
                make_float2(a[0] * sc, zim ? 0.f : a[1] * sc);
            out[((r + 8) * NM + m) * HDIM + ol] =
                make_float2(a[2] * sc, zim ? 0.f : a[3] * sc);
        }
}

// =============================================================================
// K3: score partials. grid (16 bh, 32 mc of 8 modes), block 128.
// =============================================================================
#define SROW 9
__global__ __launch_bounds__(128)
void k_scores(void) {
    const int bh = blockIdx.x;
    const int mc = blockIdx.y;          // 32 chunks of 8 modes
    const int b = bh >> 3, h = bh & 7;
    const int t = threadIdx.x;
    const int tq = t >> 4;              // 0..7
    const int tk = t & 15;              // 0..15
    __shared__ __align__(16) float2 Qr[64 * SROW], Qi[64 * SROW];
    __shared__ __align__(16) float2 Kr[64 * SROW], Ki[64 * SROW];
    ull acc[8][4];
#pragma unroll
    for (int i = 0; i < 8; ++i)
#pragma unroll
        for (int j = 0; j < 4; ++j) acc[i][j] = 0ULL;

    const int SSTRIDE4 = NM * HDIM / 2;
    for (int mm = 0; mm < 8; ++mm) {
        const int m = mc * 8 + mm;
        const long base2 = (long)(b * 64) * NM * HDIM + (long)m * HDIM + h * DH;
        for (int d0 = 0; d0 < DH; d0 += 16) {
            const float4* Qg = (const float4*)g_Qf + ((base2 + d0) >> 1);
            const float4* Kg = (const float4*)g_Kf + ((base2 + d0) >> 1);
            __syncthreads();
#pragma unroll
            for (int l = 0; l < 4; ++l) {
                int fl = t + l * 128;
                int s = fl >> 3, dp = fl & 7;
                float4 q = Qg[(long)s * SSTRIDE4 + dp];
                float4 k = Kg[(long)s * SSTRIDE4 + dp];
                Qr[s * SROW + dp] = make_float2(q.x, q.z);
                Qi[s * SROW + dp] = make_float2(q.y, q.w);
                Kr[s * SROW + dp] = make_float2(k.x, k.z);
                Ki[s * SROW + dp] = make_float2(k.y, k.w);
            }
            __syncthreads();
#pragma unroll
            for (int dp = 0; dp < 8; ++dp) {
                ull kr[4], ki[4];
#pragma unroll
                for (int j = 0; j < 4; ++j) {
                    int row = tk + 16 * j;
                    kr[j] = *(const ull*)&Kr[row * SROW + dp];
                    ki[j] = *(const ull*)&Ki[row * SROW + dp];
                }
#pragma unroll
                for (int i = 0; i < 8; ++i) {
                    int row = tq + 8 * i;
                    ull qr = *(const ull*)&Qr[row * SROW + dp];
                    ull qi = *(const ull*)&Qi[row * SROW + dp];
#pragma unroll
                    for (int j = 0; j < 4; ++j) {
                        fma2(acc[i][j], qr, kr[j]);
                        fma2(acc[i][j], qi, ki[j]);
                    }
                }
            }
        }
    }
#pragma unroll
    for (int i = 0; i < 8; ++i)
#pragma unroll
        for (int j = 0; j < 4; ++j) {
            int q = tq + 8 * i, k = tk + 16 * j;
            float2 v = u2f(acc[i][j]);
            g_part[((mc * 16 + bh) * 64 + q) * 64 + k] = v.x + v.y;
        }
}

// =============================================================================
// K_bias: Swin-v2 log-CPB MLP -> bias[h][i][j]. grid 64 (i), block 64 (j)
// =============================================================================
__global__ __launch_bounds__(64)
void k_bias(const float* __restrict__ w1, const float* __restrict__ b1,
            const float* __restrict__ w2) {
    const int i = blockIdx.x, j = threadIdx.x;
    float dx = (float)((i >> 3) - (j >> 3));
    float dy = (float)((i & 7) - (j & 7));
    float f0 = (dx > 0.f ? 1.f : (dx < 0.f ? -1.f : 0.f)) * log1pf(fabsf(dx));
    float f1 = (dy > 0.f ? 1.f : (dy < 0.f ? -1.f : 0.f)) * log1pf(fabsf(dy));
    float acc[NH];
#pragma unroll
    for (int h = 0; h < NH; ++h) acc[h] = 0.f;
    for (int hid = 0; hid < 64; ++hid) {
        float hv = fmaxf(f0 * w1[hid] + f1 * w1[64 + hid] + b1[hid], 0.f);
#pragma unroll
        for (int h = 0; h < NH; ++h) acc[h] += hv * w2[hid * NH + h];
    }
#pragma unroll
    for (int h = 0; h < NH; ++h) g_bias[(h * 64 + i) * 64 + j] = acc[h];
}

// =============================================================================
// K4: reduce partials + bias + softmax -> attn. grid 1024 rows, block 32
// =============================================================================
__global__ __launch_bounds__(32)
void k_softmax(void) {
    const int row = blockIdx.x;
    const int bh = row >> 6, q = row & 63;
    const int h = bh & 7;
    const int t = threadIdx.x;
    float v[2];
#pragma unroll
    for (int e = 0; e < 2; ++e) {
        int k = t + e * 32;
        float s = 0.f;
#pragma unroll
        for (int mc = 0; mc < NPART; ++mc)
            s += g_part[((mc * 16 + bh) * 64 + q) * 64 + k];
        v[e] = s + g_bias[(h * 64 + q) * 64 + k];
    }
    float mx = fmaxf(v[0], v[1]);
#pragma unroll
    for (int o = 16; o; o >>= 1) mx = fmaxf(mx, __shfl_xor_sync(0xffffffffu, mx, o));
    float e0 = __expf(v[0] - mx), e1 = __expf(v[1] - mx);
    float sm = e0 + e1;
#pragma unroll
    for (int o = 16; o; o >>= 1) sm += __shfl_xor_sync(0xffffffffu, sm, o);
    float inv = 1.f / sm;
    g_attn[row * 64 + t]      = e0 * inv;
    g_attn[row * 64 + t + 32] = e1 * inv;
}

// =============================================================================
// K5: SAf = attn @ Vf (FFMA2); emits bf16 hi/lo planes [m][bs][2i] for out-mma.
// grid (16 bh, 256 modes), block 256
// =============================================================================
__global__ __launch_bounds__(256)
void k_attnv(void) {
    const int bh = blockIdx.x;
    const int m  = blockIdx.y;
    const int b = bh >> 3, h = bh & 7;
    const int t = threadIdx.x;
    const int c  = t & 63;
    const int qg = t >> 6;
    __shared__ __align__(16) float  att[64][64];
    __shared__ float2 Vs[16][64];
#pragma unroll
    for (int l = 0; l < 16; ++l) {
        int j = t + l * 256;
        att[j >> 6][j & 63] = g_attn[bh * 4096 + j];
    }
    ull acc[16];
#pragma unroll
    for (int i = 0; i < 16; ++i) acc[i] = 0ULL;

    for (int k0 = 0; k0 < 64; k0 += 16) {
        __syncthreads();
#pragma unroll
        for (int l = 0; l < 4; ++l) {
            int j = t + l * 256;
            int kk = j >> 6, cc = j & 63;
            Vs[kk][cc] = g_Vf[((b * 64 + k0 + kk) * NM + m) * HDIM + h * DH + cc];
        }
        __syncthreads();
        ull vv[16];
#pragma unroll
        for (int kk = 0; kk < 16; ++kk) {
            float2 x = Vs[kk][c];
            vv[kk] = f2u(x.x, x.y);
        }
#pragma unroll
        for (int iq = 0; iq < 16; ++iq) {
            const float4* arow = (const float4*)&att[qg * 16 + iq][k0];
#pragma unroll
            for (int kq = 0; kq < 4; ++kq) {
                float4 a4 = arow[kq];
                fma2(acc[iq], bc2(a4.x), vv[kq * 4 + 0]);
                fma2(acc[iq], bc2(a4.y), vv[kq * 4 + 1]);
                fma2(acc[iq], bc2(a4.z), vv[kq * 4 + 2]);
                fma2(acc[iq], bc2(a4.w), vv[kq * 4 + 3]);
            }
        }
    }
    const int i = h * DH + c;           // complex column 0..511
#pragma unroll
    for (int iq = 0; iq < 16; ++iq) {
        int q = qg * 16 + iq;
        float2 v = u2f(acc[iq]);
        __nv_bfloat16 hr = __float2bfloat16(v.x);
        __nv_bfloat16 hi = __float2bfloat16(v.y);
        __nv_bfloat16 lr = __float2bfloat16(v.x - __bfloat162float(hr));
        __nv_bfloat16 li = __float2bfloat16(v.y - __bfloat162float(hi));
        long idx = ((long)m * BSZ + (b * 64 + q)) * 1024 + 2 * i;
        *(__nv_bfloat162*)&g_SAh[idx] = __halves2bfloat162(hr, hi);
        *(__nv_bfloat162*)&g_SAl[idx] = __halves2bfloat162(lr, li);
    }
}

// =============================================================================
// K6 (TENSOR CORE): output per-mode complex GEMM via bf16-split mma.sync.
// grid (256 modes, 4 ksplit), block 256 (8 warps 2x4). K-split partials.
// =============================================================================
__global__ __launch_bounds__(256)
void k_out_mma(const float* __restrict__ Wo) {
    const int m   = blockIdx.x;
    const int ksp = blockIdx.y;
    const float2* Wf2 = (const float2*)Wo;
    const int t = threadIdx.x;
    const int lane = t & 31, w = t >> 5;
    const int wm = w & 1, wn = w >> 1;

    __shared__ __align__(16) __nv_bfloat16 Ah[128][40];
    __shared__ __align__(16) __nv_bfloat16 Al[128][40];
    __shared__ __align__(16) __nv_bfloat16 Bh[32][136];
    __shared__ __align__(16) __nv_bfloat16 Bl[32][136];

    float acc[4][4][4];
#pragma unroll
    for (int a = 0; a < 4; ++a)
#pragma unroll
        for (int b = 0; b < 4; ++b)
#pragma unroll
            for (int c = 0; c < 4; ++c) acc[a][b][c] = 0.f;

    const uint32_t aAddrH = cvta_s(&Ah[wm * 64 + (lane & 15)][(lane >> 4) * 8]);
    const uint32_t aAddrL = cvta_s(&Al[wm * 64 + (lane & 15)][(lane >> 4) * 8]);
    const int brow = (lane & 7) + ((lane >> 3) & 1) * 8;
    const int bcol = wn * 32 + (lane >> 4) * 8;
    const uint32_t bAddrH = cvta_s(&Bh[brow][bcol]);
    const uint32_t bAddrL = cvta_s(&Bl[brow][bcol]);

    for (int kc = 0; kc < 8; ++kc) {
        const int k0 = ksp * 256 + kc * 32;  // real-k base within 1024
        const int i0 = k0 >> 1;              // complex-i base
        __syncthreads();
        // A fill: 128bs x 32k bf16 (hi & lo)
#pragma unroll
        for (int l = 0; l < 2; ++l) {
            int idx = t + l * 256;
            int bs = idx >> 2, seg = idx & 3;
            const uint4* sh = (const uint4*)(g_SAh + ((long)m * BSZ + bs) * 1024 + k0) + seg;
            const uint4* sl = (const uint4*)(g_SAl + ((long)m * BSZ + bs) * 1024 + k0) + seg;
            *(uint4*)&Ah[bs][seg * 8] = *sh;
            *(uint4*)&Al[bs][seg * 8] = *sl;
        }
        // B fill: Wo[i][co][m] gather, split hi/lo, complex 2x2 block
#pragma unroll
        for (int l = 0; l < 4; ++l) {
            int idx = t + l * 256;      // 1024 = 16i x 64o
            int i = idx >> 6, o = idx & 63;
            float2 wv = Wf2[(((i0 + i) * CI) + o) * NM + m];
            __nv_bfloat16 hr = __float2bfloat16(wv.x);
            __nv_bfloat16 hi = __float2bfloat16(wv.y);
            float lrf = wv.x - __bfloat162float(hr);
            float lif = wv.y - __bfloat162float(hi);
            __nv_bfloat16 lr  = __float2bfloat16(lrf);
            __nv_bfloat16 li  = __float2bfloat16(lif);
            __nv_bfloat16 nhi = __float2bfloat16(-wv.y);
            __nv_bfloat16 nli = __float2bfloat16(-lif);
            *(__nv_bfloat162*)&Bh[2 * i][2 * o]     = __halves2bfloat162(hr, hi);
            *(__nv_bfloat162*)&Bh[2 * i + 1][2 * o] = __halves2bfloat162(nhi, hr);
            *(__nv_bfloat162*)&Bl[2 * i][2 * o]     = __halves2bfloat162(lr, li);
            *(__nv_bfloat162*)&Bl[2 * i + 1][2 * o] = __halves2bfloat162(nli, lr);
        }
        __syncthreads();
#pragma unroll
        for (int ks = 0; ks < 2; ++ks) {
            uint32_t ah[4][4], al[4][4];
#pragma unroll
            for (int mt = 0; mt < 4; ++mt) {
                uint32_t off = (uint32_t)(mt * 16 * 40 + ks * 16) * 2;
                ldm4(aAddrH + off, ah[mt][0], ah[mt][1], ah[mt][2], ah[mt][3]);
                ldm4(aAddrL + off, al[mt][0], al[mt][1], al[mt][2], al[mt][3]);
            }
            uint32_t bh[4][2], bl[4][2];
#pragma unroll
            for (int np = 0; np < 2; ++np) {
                uint32_t off = (uint32_t)(ks * 16 * 136 + np * 16) * 2;
                uint32_t r0, r1, r2, r3;
                ldm4t(bAddrH + off, r0, r1, r2, r3);
                bh[np * 2][0] = r0; bh[np * 2][1] = r1;
                bh[np * 2 + 1][0] = r2; bh[np * 2 + 1][1] = r3;
                ldm4t(bAddrL + off, r0, r1, r2, r3);
                bl[np * 2][0] = r0; bl[np * 2][1] = r1;
                bl[np * 2 + 1][0] = r2; bl[np * 2 + 1][1] = r3;
            }
#pragma unroll
            for (int mt = 0; mt < 4; ++mt)
#pragma unroll
                for (int nt = 0; nt < 4; ++nt) {
                    mma_bf16(acc[mt][nt], ah[mt], bh[nt][0], bh[nt][1]);
                    mma_bf16(acc[mt][nt], ah[mt], bl[nt][0], bl[nt][1]);
                    mma_bf16(acc[mt][nt], al[mt], bh[nt][0], bh[nt][1]);
                }
        }
    }
    const int base = ksp * (BSZ * CI * NM);
#pragma unroll
    for (int mt = 0; mt < 4; ++mt)
#pragma unroll
        for (int nt = 0; nt < 4; ++nt) {
            int r  = wm * 64 + mt * 16 + (lane >> 2);
            int co = wn * 16 + nt * 4 + (lane & 3);
            float* a = acc[mt][nt];
            g_Outp[base + (r * CI + co) * NM + m]       = make_float2(a[0], a[1]);
            g_Outp[base + ((r + 8) * CI + co) * NM + m] = make_float2(a[2], a[3]);
        }
}

// =============================================================================
// K7: truncated inverse (irfft2 semantics) + partial reduce. grid 8192 fields
// =============================================================================
__global__ __launch_bounds__(256)
void k_inv_dft(float* __restrict__ out) {
    const int f = blockIdx.x;
    const int t = threadIdx.x;
    __shared__ float2 Z[256];
    __shared__ float2 u[32][16];
    __shared__ ull twp[32], twm[32];
    if (t < 32) {
        float sv, cv; sincospif((float)t * (1.0f / 16.0f), &sv, &cv);
        twp[t] = f2u(cv, sv);
        twm[t] = f2u(-sv, cv);
    }
    {
        float2 a = g_Outp[0 * (BSZ * CI * NM) + f * NM + t];
        float2 b = g_Outp[1 * (BSZ * CI * NM) + f * NM + t];
        float2 c = g_Outp[2 * (BSZ * CI * NM) + f * NM + t];
        float2 d = g_Outp[3 * (BSZ * CI * NM) + f * NM + t];
        Z[t] = make_float2(a.x + b.x + c.x + d.x, a.y + b.y + c.y + d.y);
    }
    __syncthreads();
    for (int o = t; o < 512; o += 256) {
        int x = o >> 4, ky = o & 15;
        ull acc = 0;
#pragma unroll
        for (int kx = 0; kx < 16; ++kx) {
            float2 z = Z[kx * 16 + ky];
            int w = (kx * x) & 31;
            fma2(acc, bc2(z.x), twp[w]);
            fma2(acc, bc2(z.y), twm[w]);
        }
        u[x][ky] = u2f(acc);
    }
    __syncthreads();
#pragma unroll
    for (int r = 0; r < 4; ++r) {
        int idx = t + r * 256;
        int x = idx >> 5, y = idx & 31;
        float a = 0.5f * u[x][0].x;
#pragma unroll
        for (int ky = 1; ky < 16; ++ky) {
            float2 uv = u[x][ky];
            float2 w = u2f(twp[(ky * y) & 31]);
            a += uv.x * w.x - uv.y * w.y;
        }
        out[f * 1024 + idx] = a * (1.0f / 512.0f);
    }
}

// =============================================================================
extern "C" void kernel_launch(void* const* d_in, const int* in_sizes, int n_in,
                              void* d_out, int out_size) {
    const float* seq = (const float*)d_in[0];
    const float* wq  = (const float*)d_in[1];
    const float* wk  = (const float*)d_in[2];
    const float* wv  = (const float*)d_in[3];
    const float* wo  = (const float*)d_in[4];
    const float* w1  = (const float*)d_in[5];
    const float* b1  = (const float*)d_in[6];
    const float* w2  = (const float*)d_in[7];
    float* out = (float*)d_out;

    k_fwd_dft<<<8192, 256>>>(seq);

    dim3 gQ(256, 8, 3);
    k_qkv_mma<<<gQ, 256>>>(wq, wk, wv);

    k_bias<<<64, 64>>>(w1, b1, w2);

    dim3 gS(16, 32);
    k_scores<<<gS, 128>>>();
    k_softmax<<<1024, 32>>>();

    dim3 gA(16, 256);
    k_attnv<<<gA, 256>>>();

    dim3 gO(256, 4);
    k_out_mma<<<gO, 256>>>(wo);
    k_inv_dft<<<8192, 256>>>(out);
}

// round 11
// speedup vs baseline: 1.9694x; 1.0500x over previous
#include <cuda_runtime.h>
#include <cuda_bf16.h>
#include <stdint.h>
#include <math.h>

// Problem constants: B=2, S=64, D=64, H=W=32, heads=8, modes 16x16
#define BSZ   128          // B*S
#define CI    64           // embed dim
#define HDIM  512          // heads*embed
#define NH    8
#define DH    64
#define NM    256          // 16x16 modes
#define NPART 32           // mode chunks for score partials (8 modes each)

typedef unsigned long long ull;

// ---------------- packed f32x2 helpers (Blackwell FFMA2) ---------------------
__device__ __forceinline__ ull f2u(float x, float y) {
    ull u; asm("mov.b64 %0, {%1,%2};" : "=l"(u) : "f"(x), "f"(y)); return u;
}
__device__ __forceinline__ ull bc2(float x) { return f2u(x, x); }
__device__ __forceinline__ void fma2(ull& d, ull a, ull b) {
    asm("fma.rn.f32x2 %0, %1, %2, %0;" : "+l"(d) : "l"(a), "l"(b));
}
__device__ __forceinline__ float2 u2f(ull u) {
    float2 v; asm("mov.b64 {%0,%1}, %2;" : "=f"(v.x), "=f"(v.y) : "l"(u)); return v;
}

// ---------------- mma.sync bf16 helpers --------------------------------------
__device__ __forceinline__ uint32_t cvta_s(const void* p) {
    return (uint32_t)__cvta_generic_to_shared(p);
}
__device__ __forceinline__ void ldm4(uint32_t a, uint32_t& r0, uint32_t& r1,
                                     uint32_t& r2, uint32_t& r3) {
    asm volatile("ldmatrix.sync.aligned.m8n8.x4.shared.b16 {%0,%1,%2,%3},[%4];"
                 : "=r"(r0), "=r"(r1), "=r"(r2), "=r"(r3) : "r"(a));
}
__device__ __forceinline__ void ldm4t(uint32_t a, uint32_t& r0, uint32_t& r1,
                                      uint32_t& r2, uint32_t& r3) {
    asm volatile("ldmatrix.sync.aligned.m8n8.x4.trans.shared.b16 {%0,%1,%2,%3},[%4];"
                 : "=r"(r0), "=r"(r1), "=r"(r2), "=r"(r3) : "r"(a));
}
__device__ __forceinline__ void mma_bf16(float* c, const uint32_t* a,
                                         uint32_t b0, uint32_t b1) {
    asm volatile("mma.sync.aligned.m16n8k16.row.col.f32.bf16.bf16.f32 "
                 "{%0,%1,%2,%3},{%4,%5,%6,%7},{%8,%9},{%0,%1,%2,%3};"
                 : "+f"(c[0]), "+f"(c[1]), "+f"(c[2]), "+f"(c[3])
                 : "r"(a[0]), "r"(a[1]), "r"(a[2]), "r"(a[3]), "r"(b0), "r"(b1));
}
__device__ __forceinline__ __nv_bfloat162 split_hi(float2 v) {
    return __halves2bfloat162(__float2bfloat16(v.x), __float2bfloat16(v.y));
}
__device__ __forceinline__ __nv_bfloat162 split_lo(float2 v) {
    float hr = __bfloat162float(__float2bfloat16(v.x));
    float hi = __bfloat162float(__float2bfloat16(v.y));
    return __halves2bfloat162(__float2bfloat16(v.x - hr), __float2bfloat16(v.y - hi));
}

// ---------------- static device scratch (no allocations allowed) -------------
__device__ __align__(16) __nv_bfloat16 g_Xh[NM * BSZ * 128]; // [m][bs][k] hi
__device__ __align__(16) __nv_bfloat16 g_Xl[NM * BSZ * 128]; // [m][bs][k] lo
__device__ __align__(16) __nv_bfloat16 g_Qph[NM * NH * BSZ * 128]; // [(m,h)][bs][2d]
__device__ __align__(16) __nv_bfloat16 g_Qpl[NM * NH * BSZ * 128];
__device__ __align__(16) __nv_bfloat16 g_Kph[NM * NH * BSZ * 128];
__device__ __align__(16) __nv_bfloat16 g_Kpl[NM * NH * BSZ * 128];
__device__ __align__(16) float2 g_Vf [BSZ * NM * HDIM];      // [bs][m][o]
__device__ __align__(16) __nv_bfloat16 g_SAh[NM * BSZ * 1024]; // [m][bs][2i] hi
__device__ __align__(16) __nv_bfloat16 g_SAl[NM * BSZ * 1024]; // [m][bs][2i] lo
__device__ __align__(16) float2 g_Outp[4 * BSZ * CI * NM];   // 4 K-split partials
__device__ float  g_part[NPART * 16 * 64 * 64];              // [mc][bh][q][k]
__device__ __align__(16) float g_attn[16 * 64 * 64];
__device__ float  g_bias[NH * 64 * 64];

// =============================================================================
// K1: truncated forward DFT; emits bf16 hi/lo split planes for the MMA GEMM.
// =============================================================================
__global__ __launch_bounds__(256)
void k_fwd_dft(const float* __restrict__ seq) {
    const int f = blockIdx.x;           // bs*64 + ci
    const int t = threadIdx.x;
    __shared__ float  s[1024];
    __shared__ float2 u[512];           // [x][ky]
    __shared__ ull twc[32], tws[32];
    if (t < 32) {
        float sv, cv; sincospif((float)t * (1.0f / 16.0f), &sv, &cv);
        twc[t] = f2u(cv, -sv);          // (c, -s)
        tws[t] = f2u(sv,  cv);          // (s,  c)
    }
#pragma unroll
    for (int l = 0; l < 4; ++l) s[t + l * 256] = seq[f * 1024 + t + l * 256];
    __syncthreads();
    for (int o = t; o < 512; o += 256) {
        int x = o >> 4, ky = o & 15;
        ull acc = 0;
#pragma unroll
        for (int y = 0; y < 32; ++y)
            fma2(acc, bc2(s[x * 32 + y]), twc[(ky * y) & 31]);
        u[o] = u2f(acc);
    }
    __syncthreads();
    {
        int kx = t >> 4, ky = t & 15;   // mode m = t
        ull acc = 0;
#pragma unroll
        for (int x = 0; x < 32; ++x) {
            float2 a = u[x * 16 + ky];
            int w = (kx * x) & 31;
            fma2(acc, bc2(a.x), twc[w]);
            fma2(acc, bc2(a.y), tws[w]);
        }
        int bs = f >> 6, ci = f & 63;
        float2 v = u2f(acc);
        int idx = (t * BSZ + bs) * 128 + 2 * ci;
        *(__nv_bfloat162*)&g_Xh[idx] = split_hi(v);
        *(__nv_bfloat162*)&g_Xl[idx] = split_lo(v);
    }
}

// =============================================================================
// K2 (TENSOR CORE): fused QKV per-mode complex GEMM via bf16-split mma.sync.
// Q/K paths emit bf16 hi/lo planes [(m,h)][bs][2d]; V emits float2 g_Vf.
// grid (256 modes, 8 o-chunks == heads, 3 paths), block 256 (8 warps 2x4)
// =============================================================================
__global__ __launch_bounds__(256)
void k_qkv_mma(const float* __restrict__ Wq, const float* __restrict__ Wk,
               const float* __restrict__ Wv) {
    const int m  = blockIdx.x;
    const int oc = blockIdx.y;          // == head for Q/K paths
    const int z  = blockIdx.z;
    const float2* Wf2 = (const float2*)((z == 0) ? Wq : (z == 1) ? Wk : Wv);
    const int t = threadIdx.x;
    const int lane = t & 31, w = t >> 5;
    const int wm = w & 1, wn = w >> 1;  // warp grid 2 x 4

    __shared__ __align__(16) __nv_bfloat16 Ah[128][40];
    __shared__ __align__(16) __nv_bfloat16 Al[128][40];
    __shared__ __align__(16) __nv_bfloat16 Bh[32][136];
    __shared__ __align__(16) __nv_bfloat16 Bl[32][136];

    float acc[4][4][4];
#pragma unroll
    for (int a = 0; a < 4; ++a)
#pragma unroll
        for (int b = 0; b < 4; ++b)
#pragma unroll
            for (int c = 0; c < 4; ++c) acc[a][b][c] = 0.f;

    const uint32_t aAddrH = cvta_s(&Ah[wm * 64 + (lane & 15)][(lane >> 4) * 8]);
    const uint32_t aAddrL = cvta_s(&Al[wm * 64 + (lane & 15)][(lane >> 4) * 8]);
    const int brow = (lane & 7) + ((lane >> 3) & 1) * 8;
    const int bcol = wn * 32 + (lane >> 4) * 8;
    const uint32_t bAddrH = cvta_s(&Bh[brow][bcol]);
    const uint32_t bAddrL = cvta_s(&Bl[brow][bcol]);

    for (int kc = 0; kc < 4; ++kc) {
        const int k0 = kc * 32, i0 = kc * 16;
        __syncthreads();
#pragma unroll
        for (int l = 0; l < 2; ++l) {
            int idx = t + l * 256;      // 512 uint4
            int bs = idx >> 2, seg = idx & 3;
            const uint4* sh = (const uint4*)(g_Xh + (m * BSZ + bs) * 128 + k0) + seg;
            const uint4* sl = (const uint4*)(g_Xl + (m * BSZ + bs) * 128 + k0) + seg;
            *(uint4*)&Ah[bs][seg * 8] = *sh;
            *(uint4*)&Al[bs][seg * 8] = *sl;
        }
#pragma unroll
        for (int l = 0; l < 4; ++l) {
            int idx = t + l * 256;      // 1024 = 16i x 64o
            int i = idx >> 6, o = idx & 63;
            float2 wv = Wf2[(((i0 + i) * HDIM) + oc * 64 + o) * NM + m];
            __nv_bfloat16 hr = __float2bfloat16(wv.x);
            __nv_bfloat16 hi = __float2bfloat16(wv.y);
            float lrf = wv.x - __bfloat162float(hr);
            float lif = wv.y - __bfloat162float(hi);
            __nv_bfloat16 lr  = __float2bfloat16(lrf);
            __nv_bfloat16 li  = __float2bfloat16(lif);
            __nv_bfloat16 nhi = __float2bfloat16(-wv.y);
            __nv_bfloat16 nli = __float2bfloat16(-lif);
            *(__nv_bfloat162*)&Bh[2 * i][2 * o]     = __halves2bfloat162(hr, hi);
            *(__nv_bfloat162*)&Bh[2 * i + 1][2 * o] = __halves2bfloat162(nhi, hr);
            *(__nv_bfloat162*)&Bl[2 * i][2 * o]     = __halves2bfloat162(lr, li);
            *(__nv_bfloat162*)&Bl[2 * i + 1][2 * o] = __halves2bfloat162(nli, lr);
        }
        __syncthreads();
#pragma unroll
        for (int ks = 0; ks < 2; ++ks) {
            uint32_t ah[4][4], al[4][4];
#pragma unroll
            for (int mt = 0; mt < 4; ++mt) {
                uint32_t off = (uint32_t)(mt * 16 * 40 + ks * 16) * 2;
                ldm4(aAddrH + off, ah[mt][0], ah[mt][1], ah[mt][2], ah[mt][3]);
                ldm4(aAddrL + off, al[mt][0], al[mt][1], al[mt][2], al[mt][3]);
            }
            uint32_t bh[4][2], bl[4][2];
#pragma unroll
            for (int np = 0; np < 2; ++np) {
                uint32_t off = (uint32_t)(ks * 16 * 136 + np * 16) * 2;
                uint32_t r0, r1, r2, r3;
                ldm4t(bAddrH + off, r0, r1, r2, r3);
                bh[np * 2][0] = r0; bh[np * 2][1] = r1;
                bh[np * 2 + 1][0] = r2; bh[np * 2 + 1][1] = r3;
                ldm4t(bAddrL + off, r0, r1, r2, r3);
                bl[np * 2][0] = r0; bl[np * 2][1] = r1;
                bl[np * 2 + 1][0] = r2; bl[np * 2 + 1][1] = r3;
            }
#pragma unroll
            for (int mt = 0; mt < 4; ++mt)
#pragma unroll
                for (int nt = 0; nt < 4; ++nt) {
                    mma_bf16(acc[mt][nt], ah[mt], bh[nt][0], bh[nt][1]);
                    mma_bf16(acc[mt][nt], ah[mt], bl[nt][0], bl[nt][1]);
                    mma_bf16(acc[mt][nt], al[mt], bh[nt][0], bh[nt][1]);
                }
        }
    }
    float sc = 1.f; bool zim = false;
    if (z == 0) {                       // Q: Parseval weight * softmax scale
        float wgt = (m == 0) ? 1.f : (((m & 15) == 0) ? 0.5f : 2.f);
        sc = wgt * (1.f / 262144.f); zim = (m == 0);
    } else if (z == 2) {                // V: Hermitian roundtrip projection
        if (m == 0) zim = true;
        else if ((m & 15) == 0) sc = 0.5f;
    }
    if (z == 2) {
#pragma unroll
        for (int mt = 0; mt < 4; ++mt)
#pragma unroll
            for (int nt = 0; nt < 4; ++nt) {
                int r  = wm * 64 + mt * 16 + (lane >> 2);
                int ol = oc * 64 + wn * 16 + nt * 4 + (lane & 3);
                float* a = acc[mt][nt];
                g_Vf[(r * NM + m) * HDIM + ol] =
                    make_float2(a[0] * sc, zim ? 0.f : a[1] * sc);
                g_Vf[((r + 8) * NM + m) * HDIM + ol] =
                    make_float2(a[2] * sc, zim ? 0.f : a[3] * sc);
            }
    } else {
        __nv_bfloat16* ph = (z == 0) ? g_Qph : g_Kph;
        __nv_bfloat16* pl = (z == 0) ? g_Qpl : g_Kpl;
        const long pb = (long)(m * NH + oc) * BSZ;
#pragma unroll
        for (int mt = 0; mt < 4; ++mt)
#pragma unroll
            for (int nt = 0; nt < 4; ++nt) {
                int r  = wm * 64 + mt * 16 + (lane >> 2);
                int cl = wn * 16 + nt * 4 + (lane & 3);   // head-local complex col
                float* a = acc[mt][nt];
                float2 v0 = make_float2(a[0] * sc, zim ? 0.f : a[1] * sc);
                float2 v1 = make_float2(a[2] * sc, zim ? 0.f : a[3] * sc);
                long i0x = (pb + r) * 128 + 2 * cl;
                long i1x = (pb + r + 8) * 128 + 2 * cl;
                *(__nv_bfloat162*)&ph[i0x] = split_hi(v0);
                *(__nv_bfloat162*)&pl[i0x] = split_lo(v0);
                *(__nv_bfloat162*)&ph[i1x] = split_hi(v1);
                *(__nv_bfloat162*)&pl[i1x] = split_lo(v1);
            }
    }
}

// =============================================================================
// K3 (TENSOR CORE): score partials via bf16-split mma.
// grid (16 bh, 32 mc of 8 modes), block 128 (4 warps, each 16q x 64s).
// C[64q x 64s] += Q_plane[64 x 128] . K_plane[64 x 128]^T per (mode,head).
// =============================================================================
__global__ __launch_bounds__(128)
void k_scores_mma(void) {
    const int bh = blockIdx.x;
    const int mc = blockIdx.y;
    const int b = bh >> 3, h = bh & 7;
    const int t = threadIdx.x;
    const int lane = t & 31, w = t >> 5;

    __shared__ __align__(16) __nv_bfloat16 Qh[64][72];
    __shared__ __align__(16) __nv_bfloat16 Ql[64][72];
    __shared__ __align__(16) __nv_bfloat16 Kh[64][72];
    __shared__ __align__(16) __nv_bfloat16 Kl[64][72];

    float acc[8][4];
#pragma unroll
    for (int i = 0; i < 8; ++i)
#pragma unroll
        for (int j = 0; j < 4; ++j) acc[i][j] = 0.f;

    const uint32_t aH = cvta_s(&Qh[w * 16 + (lane & 15)][(lane >> 4) * 8]);
    const uint32_t aL = cvta_s(&Ql[w * 16 + (lane & 15)][(lane >> 4) * 8]);
    const uint32_t bH = cvta_s(&Kh[lane & 15][(lane >> 4) * 8]);
    const uint32_t bL = cvta_s(&Kl[lane & 15][(lane >> 4) * 8]);

    for (int mm = 0; mm < 8; ++mm) {
        const int m = mc * 8 + mm;
        const long pb = (long)(m * NH + h) * BSZ + b * 64;
        for (int kc = 0; kc < 2; ++kc) {
            const int k0 = kc * 64;
            __syncthreads();
#pragma unroll
            for (int l = 0; l < 4; ++l) {
                int idx = t + l * 128;      // 512 = 64 rows x 8 seg
                int row = idx >> 3, seg = idx & 7;
                long g = (pb + row) * 128 + k0 + seg * 8;
                *(uint4*)&Qh[row][seg * 8] = *(const uint4*)&g_Qph[g];
                *(uint4*)&Ql[row][seg * 8] = *(const uint4*)&g_Qpl[g];
                *(uint4*)&Kh[row][seg * 8] = *(const uint4*)&g_Kph[g];
                *(uint4*)&Kl[row][seg * 8] = *(const uint4*)&g_Kpl[g];
            }
            __syncthreads();
#pragma unroll
            for (int ks = 0; ks < 4; ++ks) {
                uint32_t ah[4], al[4];
                ldm4(aH + ks * 32, ah[0], ah[1], ah[2], ah[3]);
                ldm4(aL + ks * 32, al[0], al[1], al[2], al[3]);
                uint32_t bhf[8][2], blf[8][2];
#pragma unroll
                for (int np = 0; np < 4; ++np) {
                    uint32_t r0, r1, r2, r3;
                    ldm4(bH + (uint32_t)(np * 16 * 144) + ks * 32, r0, r1, r2, r3);
                    bhf[np * 2][0] = r0; bhf[np * 2][1] = r2;
                    bhf[np * 2 + 1][0] = r1; bhf[np * 2 + 1][1] = r3;
                    ldm4(bL + (uint32_t)(np * 16 * 144) + ks * 32, r0, r1, r2, r3);
                    blf[np * 2][0] = r0; blf[np * 2][1] = r2;
                    blf[np * 2 + 1][0] = r1; blf[np * 2 + 1][1] = r3;
                }
#pragma unroll
                for (int nt = 0; nt < 8; ++nt) {
                    mma_bf16(acc[nt], ah, bhf[nt][0], bhf[nt][1]);
                    mma_bf16(acc[nt], ah, blf[nt][0], blf[nt][1]);
                    mma_bf16(acc[nt], al, bhf[nt][0], bhf[nt][1]);
                }
            }
        }
    }
    const int q0 = w * 16 + (lane >> 2);
    const int cb = 2 * (lane & 3);
    float* dst = &g_part[((mc * 16 + bh) * 64) * 64];
#pragma unroll
    for (int nt = 0; nt < 8; ++nt) {
        int col = nt * 8 + cb;
        *(float2*)&dst[q0 * 64 + col]       = make_float2(acc[nt][0], acc[nt][1]);
        *(float2*)&dst[(q0 + 8) * 64 + col] = make_float2(acc[nt][2], acc[nt][3]);
    }
}

// =============================================================================
// K_bias: Swin-v2 log-CPB MLP -> bias[h][i][j]. grid 64 (i), block 64 (j)
// =============================================================================
__global__ __launch_bounds__(64)
void k_bias(const float* __restrict__ w1, const float* __restrict__ b1,
            const float* __restrict__ w2) {
    const int i = blockIdx.x, j = threadIdx.x;
    float dx = (float)((i >> 3) - (j >> 3));
    float dy = (float)((i & 7) - (j & 7));
    float f0 = (dx > 0.f ? 1.f : (dx < 0.f ? -1.f : 0.f)) * log1pf(fabsf(dx));
    float f1 = (dy > 0.f ? 1.f : (dy < 0.f ? -1.f : 0.f)) * log1pf(fabsf(dy));
    float acc[NH];
#pragma unroll
    for (int h = 0; h < NH; ++h) acc[h] = 0.f;
    for (int hid = 0; hid < 64; ++hid) {
        float hv = fmaxf(f0 * w1[hid] + f1 * w1[64 + hid] + b1[hid], 0.f);
#pragma unroll
        for (int h = 0; h < NH; ++h) acc[h] += hv * w2[hid * NH + h];
    }
#pragma unroll
    for (int h = 0; h < NH; ++h) g_bias[(h * 64 + i) * 64 + j] = acc[h];
}

// =============================================================================
// K4: reduce partials + bias + softmax -> attn. grid 1024 rows, block 32
// =============================================================================
__global__ __launch_bounds__(32)
void k_softmax(void) {
    const int row = blockIdx.x;
    const int bh = row >> 6, q = row & 63;
    const int h = bh & 7;
    const int t = threadIdx.x;
    float v[2];
#pragma unroll
    for (int e = 0; e < 2; ++e) {
        int k = t + e * 32;
        float s = 0.f;
#pragma unroll
        for (int mc = 0; mc < NPART; ++mc)
            s += g_part[((mc * 16 + bh) * 64 + q) * 64 + k];
        v[e] = s + g_bias[(h * 64 + q) * 64 + k];
    }
    float mx = fmaxf(v[0], v[1]);
#pragma unroll
    for (int o = 16; o; o >>= 1) mx = fmaxf(mx, __shfl_xor_sync(0xffffffffu, mx, o));
    float e0 = __expf(v[0] - mx), e1 = __expf(v[1] - mx);
    float sm = e0 + e1;
#pragma unroll
    for (int o = 16; o; o >>= 1) sm += __shfl_xor_sync(0xffffffffu, sm, o);
    float inv = 1.f / sm;
    g_attn[row * 64 + t]      = e0 * inv;
    g_attn[row * 64 + t + 32] = e1 * inv;
}

// =============================================================================
// K5: SAf = attn @ Vf (FFMA2); emits bf16 hi/lo planes [m][bs][2i] for out-mma.
// grid (16 bh, 256 modes), block 256
// =============================================================================
__global__ __launch_bounds__(256)
void k_attnv(void) {
    const int bh = blockIdx.x;
    const int m  = blockIdx.y;
    const int b = bh >> 3, h = bh & 7;
    const int t = threadIdx.x;
    const int c  = t & 63;
    const int qg = t >> 6;
    __shared__ __align__(16) float  att[64][64];
    __shared__ float2 Vs[16][64];
#pragma unroll
    for (int l = 0; l < 16; ++l) {
        int j = t + l * 256;
        att[j >> 6][j & 63] = g_attn[bh * 4096 + j];
    }
    ull acc[16];
#pragma unroll
    for (int i = 0; i < 16; ++i) acc[i] = 0ULL;

    for (int k0 = 0; k0 < 64; k0 += 16) {
        __syncthreads();
#pragma unroll
        for (int l = 0; l < 4; ++l) {
            int j = t + l * 256;
            int kk = j >> 6, cc = j & 63;
            Vs[kk][cc] = g_Vf[((b * 64 + k0 + kk) * NM + m) * HDIM + h * DH + cc];
        }
        __syncthreads();
        ull vv[16];
#pragma unroll
        for (int kk = 0; kk < 16; ++kk) {
            float2 x = Vs[kk][c];
            vv[kk] = f2u(x.x, x.y);
        }
#pragma unroll
        for (int iq = 0; iq < 16; ++iq) {
            const float4* arow = (const float4*)&att[qg * 16 + iq][k0];
#pragma unroll
            for (int kq = 0; kq < 4; ++kq) {
                float4 a4 = arow[kq];
                fma2(acc[iq], bc2(a4.x), vv[kq * 4 + 0]);
                fma2(acc[iq], bc2(a4.y), vv[kq * 4 + 1]);
                fma2(acc[iq], bc2(a4.z), vv[kq * 4 + 2]);
                fma2(acc[iq], bc2(a4.w), vv[kq * 4 + 3]);
            }
        }
    }
    const int i = h * DH + c;           // complex column 0..511
#pragma unroll
    for (int iq = 0; iq < 16; ++iq) {
        int q = qg * 16 + iq;
        float2 v = u2f(acc[iq]);
        long idx = ((long)m * BSZ + (b * 64 + q)) * 1024 + 2 * i;
        *(__nv_bfloat162*)&g_SAh[idx] = split_hi(v);
        *(__nv_bfloat162*)&g_SAl[idx] = split_lo(v);
    }
}

// =============================================================================
// K6 (TENSOR CORE): output per-mode complex GEMM via bf16-split mma.sync.
// grid (256 modes, 4 ksplit), block 256 (8 warps 2x4). K-split partials.
// =============================================================================
__global__ __launch_bounds__(256)
void k_out_mma(const float* __restrict__ Wo) {
    const int m   = blockIdx.x;
    const int ksp = blockIdx.y;
    const float2* Wf2 = (const float2*)Wo;
    const int t = threadIdx.x;
    const int lane = t & 31, w = t >> 5;
    const int wm = w & 1, wn = w >> 1;

    __shared__ __align__(16) __nv_bfloat16 Ah[128][40];
    __shared__ __align__(16) __nv_bfloat16 Al[128][40];
    __shared__ __align__(16) __nv_bfloat16 Bh[32][136];
    __shared__ __align__(16) __nv_bfloat16 Bl[32][136];

    float acc[4][4][4];
#pragma unroll
    for (int a = 0; a < 4; ++a)
#pragma unroll
        for (int b = 0; b < 4; ++b)
#pragma unroll
            for (int c = 0; c < 4; ++c) acc[a][b][c] = 0.f;

    const uint32_t aAddrH = cvta_s(&Ah[wm * 64 + (lane & 15)][(lane >> 4) * 8]);
    const uint32_t aAddrL = cvta_s(&Al[wm * 64 + (lane & 15)][(lane >> 4) * 8]);
    const int brow = (lane & 7) + ((lane >> 3) & 1) * 8;
    const int bcol = wn * 32 + (lane >> 4) * 8;
    const uint32_t bAddrH = cvta_s(&Bh[brow][bcol]);
    const uint32_t bAddrL = cvta_s(&Bl[brow][bcol]);

    for (int kc = 0; kc < 8; ++kc) {
        const int k0 = ksp * 256 + kc * 32;  // real-k base within 1024
        const int i0 = k0 >> 1;              // complex-i base
        __syncthreads();
#pragma unroll
        for (int l = 0; l < 2; ++l) {
            int idx = t + l * 256;
            int bs = idx >> 2, seg = idx & 3;
            const uint4* sh = (const uint4*)(g_SAh + ((long)m * BSZ + bs) * 1024 + k0) + seg;
            const uint4* sl = (const uint4*)(g_SAl + ((long)m * BSZ + bs) * 1024 + k0) + seg;
            *(uint4*)&Ah[bs][seg * 8] = *sh;
            *(uint4*)&Al[bs][seg * 8] = *sl;
        }
#pragma unroll
        for (int l = 0; l < 4; ++l) {
            int idx = t + l * 256;      // 1024 = 16i x 64o
            int i = idx >> 6, o = idx & 63;
            float2 wv = Wf2[(((i0 + i) * CI) + o) * NM + m];
            __nv_bfloat16 hr = __float2bfloat16(wv.x);
            __nv_bfloat16 hi = __float2bfloat16(wv.y);
            float lrf = wv.x - __bfloat162float(hr);
            float lif = wv.y - __bfloat162float(hi);
            __nv_bfloat16 lr  = __float2bfloat16(lrf);
            __nv_bfloat16 li  = __float2bfloat16(lif);
            __nv_bfloat16 nhi = __float2bfloat16(-wv.y);
            __nv_bfloat16 nli = __float2bfloat16(-lif);
            *(__nv_bfloat162*)&Bh[2 * i][2 * o]     = __halves2bfloat162(hr, hi);
            *(__nv_bfloat162*)&Bh[2 * i + 1][2 * o] = __halves2bfloat162(nhi, hr);
            *(__nv_bfloat162*)&Bl[2 * i][2 * o]     = __halves2bfloat162(lr, li);
            *(__nv_bfloat162*)&Bl[2 * i + 1][2 * o] = __halves2bfloat162(nli, lr);
        }
        __syncthreads();
#pragma unroll
        for (int ks = 0; ks < 2; ++ks) {
            uint32_t ah[4][4], al[4][4];
#pragma unroll
            for (int mt = 0; mt < 4; ++mt) {
                uint32_t off = (uint32_t)(mt * 16 * 40 + ks * 16) * 2;
                ldm4(aAddrH + off, ah[mt][0], ah[mt][1], ah[mt][2], ah[mt][3]);
                ldm4(aAddrL + off, al[mt][0], al[mt][1], al[mt][2], al[mt][3]);
            }
            uint32_t bh[4][2], bl[4][2];
#pragma unroll
            for (int np = 0; np < 2; ++np) {
                uint32_t off = (uint32_t)(ks * 16 * 136 + np * 16) * 2;
                uint32_t r0, r1, r2, r3;
                ldm4t(bAddrH + off, r0, r1, r2, r3);
                bh[np * 2][0] = r0; bh[np * 2][1] = r1;
                bh[np * 2 + 1][0] = r2; bh[np * 2 + 1][1] = r3;
                ldm4t(bAddrL + off, r0, r1, r2, r3);
                bl[np * 2][0] = r0; bl[np * 2][1] = r1;
                bl[np * 2 + 1][0] = r2; bl[np * 2 + 1][1] = r3;
            }
#pragma unroll
            for (int mt = 0; mt < 4; ++mt)
#pragma unroll
                for (int nt = 0; nt < 4; ++nt) {
                    mma_bf16(acc[mt][nt], ah[mt], bh[nt][0], bh[nt][1]);
                    mma_bf16(acc[mt][nt], ah[mt], bl[nt][0], bl[nt][1]);
                    mma_bf16(acc[mt][nt], al[mt], bh[nt][0], bh[nt][1]);
                }
        }
    }
    const int base = ksp * (BSZ * CI * NM);
#pragma unroll
    for (int mt = 0; mt < 4; ++mt)
#pragma unroll
        for (int nt = 0; nt < 4; ++nt) {
            int r  = wm * 64 + mt * 16 + (lane >> 2);
            int co = wn * 16 + nt * 4 + (lane & 3);
            float* a = acc[mt][nt];
            g_Outp[base + (r * CI + co) * NM + m]       = make_float2(a[0], a[1]);
            g_Outp[base + ((r + 8) * CI + co) * NM + m] = make_float2(a[2], a[3]);
        }
}

// =============================================================================
// K7: truncated inverse (irfft2 semantics) + partial reduce. grid 8192 fields
// =============================================================================
__global__ __launch_bounds__(256)
void k_inv_dft(float* __restrict__ out) {
    const int f = blockIdx.x;
    const int t = threadIdx.x;
    __shared__ float2 Z[256];
    __shared__ float2 u[32][16];
    __shared__ ull twp[32], twm[32];
    if (t < 32) {
        float sv, cv; sincospif((float)t * (1.0f / 16.0f), &sv, &cv);
        twp[t] = f2u(cv, sv);
        twm[t] = f2u(-sv, cv);
    }
    {
        float2 a = g_Outp[0 * (BSZ * CI * NM) + f * NM + t];
        float2 b = g_Outp[1 * (BSZ * CI * NM) + f * NM + t];
        float2 c = g_Outp[2 * (BSZ * CI * NM) + f * NM + t];
        float2 d = g_Outp[3 * (BSZ * CI * NM) + f * NM + t];
        Z[t] = make_float2(a.x + b.x + c.x + d.x, a.y + b.y + c.y + d.y);
    }
    __syncthreads();
    for (int o = t; o < 512; o += 256) {
        int x = o >> 4, ky = o & 15;
        ull acc = 0;
#pragma unroll
        for (int kx = 0; kx < 16; ++kx) {
            float2 z = Z[kx * 16 + ky];
            int w = (kx * x) & 31;
            fma2(acc, bc2(z.x), twp[w]);
            fma2(acc, bc2(z.y), twm[w]);
        }
        u[x][ky] = u2f(acc);
    }
    __syncthreads();
#pragma unroll
    for (int r = 0; r < 4; ++r) {
        int idx = t + r * 256;
        int x = idx >> 5, y = idx & 31;
        float a = 0.5f * u[x][0].x;
#pragma unroll
        for (int ky = 1; ky < 16; ++ky) {
            float2 uv = u[x][ky];
            float2 w = u2f(twp[(ky * y) & 31]);
            a += uv.x * w.x - uv.y * w.y;
        }
        out[f * 1024 + idx] = a * (1.0f / 512.0f);
    }
}

// =============================================================================
extern "C" void kernel_launch(void* const* d_in, const int* in_sizes, int n_in,
                              void* d_out, int out_size) {
    const float* seq = (const float*)d_in[0];
    const float* wq  = (const float*)d_in[1];
    const float* wk  = (const float*)d_in[2];
    const float* wv  = (const float*)d_in[3];
    const float* wo  = (const float*)d_in[4];
    const float* w1  = (const float*)d_in[5];
    const float* b1  = (const float*)d_in[6];
    const float* w2  = (const float*)d_in[7];
    float* out = (float*)d_out;

    k_fwd_dft<<<8192, 256>>>(seq);

    dim3 gQ(256, 8, 3);
    k_qkv_mma<<<gQ, 256>>>(wq, wk, wv);

    k_bias<<<64, 64>>>(w1, b1, w2);

    dim3 gS(16, 32);
    k_scores_mma<<<gS, 128>>>();
    k_softmax<<<1024, 32>>>();

    dim3 gA(16, 256);
    k_attnv<<<gA, 256>>>();

    dim3 gO(256, 4);
    k_out_mma<<<gO, 256>>>(wo);
    k_inv_dft<<<8192, 256>>>(out);
}